// round 7
// baseline (speedup 1.0000x reference)
#include <cuda_runtime.h>
#include <math.h>

#define B 8
#define T 2048
#define H 1024
#define V 256
#define GRID 128
#define NTHR 512
#define UPC 8            // hidden units per CTA (2 warps per unit)

typedef unsigned long long ull;

#define PPC 16                   // positions per CTA in loss kernel
#define LOSS_GRID ((B*T)/PPC)    // 1024
#define LOSS_SMEM_FLOATS (PPC*1024 + PPC*256 + PPC)
#define LOSS_SMEM_BYTES  (LOSS_SMEM_FLOATS * 4)

#define FLAG_STRIDE 8            // 32-byte padded flags (one sector each)

// ---------------- device scratch (static; no allocation) ----------------
__device__ float    g_hs[B * T * H];           // hidden states, layout [t][b][j]
__device__ float    g_hbuf[2][B][H];           // double-buffered h
__device__ unsigned g_flags[GRID * FLAG_STRIDE]; // padded per-CTA step counters
__device__ float    g_partials[LOSS_GRID];     // per-CTA NLL partial sums

// ---------------- packed f32x2 + sync helpers ----------------
__device__ __forceinline__ ull fma2(ull a, ull b, ull c) {
    ull d;
    asm("fma.rn.f32x2 %0, %1, %2, %3;" : "=l"(d) : "l"(a), "l"(b), "l"(c));
    return d;
}
__device__ __forceinline__ float2 unpk(ull v) {
    float2 r;
    asm("mov.b64 {%0, %1}, %2;" : "=f"(r.x), "=f"(r.y) : "l"(v));
    return r;
}
__device__ __forceinline__ unsigned ld_cgv(const unsigned* p) {
    unsigned v;
    asm volatile("ld.global.cg.u32 %0, [%1];" : "=r"(v) : "l"(p));
    return v;
}
__device__ __forceinline__ void st_rel(unsigned* p, unsigned v) {
    asm volatile("st.release.gpu.global.u32 [%0], %1;" :: "l"(p), "r"(v) : "memory");
}
__device__ __forceinline__ float tanh_fast(float x) {
    return 2.0f / (1.0f + __expf(-2.0f * x)) - 1.0f;
}
__device__ __forceinline__ float sigmoid_fast(float x) {
    return 1.0f / (1.0f + __expf(-x));
}

// ---------------- reset: zero flags + h0 ----------------
__global__ void reset_kernel() {
    int tid = threadIdx.x;
    for (int i = tid; i < GRID * FLAG_STRIDE; i += blockDim.x) g_flags[i] = 0u;
    float* h0 = (float*)g_hbuf;
    for (int i = tid; i < B * H; i += blockDim.x) h0[i] = 0.0f;
}

// ---------------- persistent LSTM kernel ----------------
// 512 threads, 16 warps. Unit u = wid>>1, K-half = wid&1.
// h SMEM layout per batch row (256 float4): pos = half*128 + g*32 + lane,
// holding logical float4 group (half*128 + lane*4 + g): contiguous,
// conflict-free lane-consecutive loads with immediate offsets.
__global__ void __launch_bounds__(NTHR, 1)
lstm_kernel(const int* __restrict__ Xs,
            const float* __restrict__ W_ih,
            const float* __restrict__ W_hh,
            const float* __restrict__ b_ih,
            const float* __restrict__ b_hh)
{
    __shared__ float4 h4s[B * 256];          // 32 KB
    __shared__ float  scr[16][32];           // per-warp partial gate sums
    __shared__ float  bias_s[UPC * 4];

    const int tid   = threadIdx.x;
    const int wid   = tid >> 5;
    const int lane  = tid & 31;
    const int u     = wid >> 1;              // unit within CTA
    const int halfk = wid & 1;               // K half: 0 -> [0,512), 1 -> [512,1024)
    const int j0    = blockIdx.x * UPC;
    const int j     = j0 + u;
    const int cta   = blockIdx.x;

    // poll targets, hoisted
    const unsigned* fl0 = &g_flags[(lane)      * FLAG_STRIDE];
    const unsigned* fl1 = &g_flags[(lane + 32) * FLAG_STRIDE];
    const unsigned* fl2 = &g_flags[(lane + 64) * FLAG_STRIDE];
    const unsigned* fl3 = &g_flags[(lane + 96) * FLAG_STRIDE];

    // ---- load this thread's 64 weight floats (16 per gate) into registers ----
    ull w2[4][8];
    #pragma unroll
    for (int g = 0; g < 4; ++g) {
        const ulonglong2* src =
            (const ulonglong2*)&W_hh[(g * H + j) * H + halfk * 512 + lane * 16];
        #pragma unroll
        for (int m = 0; m < 4; ++m) {
            ulonglong2 tt = src[m];
            w2[g][2*m]   = tt.x;
            w2[g][2*m+1] = tt.y;
        }
    }
    if (tid < UPC * 4) {
        int uu = tid >> 2, g = tid & 3;
        bias_s[tid] = b_ih[g * H + j0 + uu] + b_hh[g * H + j0 + uu];
    }
    __syncthreads();

    const bool epi = (halfk == 0) && (lane < 8);   // epilogue thread for (b=lane, j)
    float c_reg = 0.0f;

    // compute-phase base pointer (float4 units): fold lane in once
    const float4* hrow0 = h4s + halfk * 128 + lane;

    for (int t = 0; t < T; ++t) {
        // ---- prefetch input contribution (independent of h_t) ----
        float wi0 = 0.f, wi1 = 0.f, wi2 = 0.f, wi3 = 0.f;
        if (epi) {
            int x = __ldg(&Xs[lane * T + t]);
            wi0 = __ldg(&W_ih[(0*H + j) * V + x]);
            wi1 = __ldg(&W_ih[(1*H + j) * V + x]);
            wi2 = __ldg(&W_ih[(2*H + j) * V + x]);
            wi3 = __ldg(&W_ih[(3*H + j) * V + x]);
        }

        // ---- wait: warp 0 polls all 128 padded flags (4 per lane) ----
        if (t > 0) {
            if (wid == 0) {
                const unsigned tgt = (unsigned)t;
                bool d0 = false, d1 = false, d2 = false, d3 = false;
                while (true) {
                    if (!d0) d0 = ld_cgv(fl0) >= tgt;
                    if (!d1) d1 = ld_cgv(fl1) >= tgt;
                    if (!d2) d2 = ld_cgv(fl2) >= tgt;
                    if (!d3) d3 = ld_cgv(fl3) >= tgt;
                    if (__all_sync(0xffffffffu, d0 && d1 && d2 && d3)) break;
                    __nanosleep(32);
                }
                asm volatile("fence.acq_rel.gpu;" ::: "memory");
            }
            __syncthreads();
        }

        // ---- stage h_t into SMEM (4 float4 per thread) ----
        {
            const float4* hb = (const float4*)g_hbuf[t & 1];
            #pragma unroll
            for (int q = 0; q < 4; ++q) {
                int k4  = tid + q * NTHR;
                int b2  = k4 >> 8;
                int r   = k4 & 255;
                int pos = (r & 128) + ((r & 3) << 5) + ((r & 127) >> 2);
                h4s[b2 * 256 + pos] = __ldcg(hb + k4);
            }
        }
        __syncthreads();

        // ---- gate partials: 256 FFMA2 per thread, immediate-offset LDS ----
        float v[32];
        #pragma unroll
        for (int b = 0; b < B; ++b) {
            ull a0 = 0ull, a1 = 0ull, a2 = 0ull, a3 = 0ull;
            const float4* hrow = hrow0 + b * 256;
            #pragma unroll
            for (int g = 0; g < 4; ++g) {
                ulonglong2 hv = *(const ulonglong2*)(hrow + g * 32);
                a0 = fma2(w2[0][2*g],   hv.x, a0);
                a1 = fma2(w2[1][2*g],   hv.x, a1);
                a2 = fma2(w2[2][2*g],   hv.x, a2);
                a3 = fma2(w2[3][2*g],   hv.x, a3);
                a0 = fma2(w2[0][2*g+1], hv.y, a0);
                a1 = fma2(w2[1][2*g+1], hv.y, a1);
                a2 = fma2(w2[2][2*g+1], hv.y, a2);
                a3 = fma2(w2[3][2*g+1], hv.y, a3);
            }
            float2 f0 = unpk(a0), f1 = unpk(a1), f2 = unpk(a2), f3 = unpk(a3);
            v[0*8 + b] = f0.x + f0.y;
            v[1*8 + b] = f1.x + f1.y;
            v[2*8 + b] = f2.x + f2.y;
            v[3*8 + b] = f3.x + f3.y;
        }

        // ---- multi-value butterfly over 32 lanes ----
        #pragma unroll
        for (int s = 0; s < 5; ++s) {
            const int m   = 1 << s;
            const int cnt = 16 >> s;
            const bool up = (lane & m) != 0;
            #pragma unroll
            for (int i = 0; i < cnt; ++i) {
                float send = up ? v[i] : v[i + cnt];
                float recv = __shfl_xor_sync(0xffffffffu, send, m);
                float keep = up ? v[i + cnt] : v[i];
                v[i] = keep + recv;
            }
        }
        {
            int o = (int)(__brev((unsigned)lane) >> 27);   // o = g*8 + b
            scr[wid][o] = v[0];
        }
        // pair barrier: warps (2u, 2u+1), 64 threads, named barrier id u+1
        asm volatile("bar.sync %0, 64;" :: "r"(u + 1) : "memory");

        float hnew = 0.0f;
        if (epi) {
            const int b = lane;
            float g0 = scr[wid][0*8+b] + scr[wid+1][0*8+b] + wi0 + bias_s[u*4+0];
            float g1 = scr[wid][1*8+b] + scr[wid+1][1*8+b] + wi1 + bias_s[u*4+1];
            float g2 = scr[wid][2*8+b] + scr[wid+1][2*8+b] + wi2 + bias_s[u*4+2];
            float g3 = scr[wid][3*8+b] + scr[wid+1][3*8+b] + wi3 + bias_s[u*4+3];
            float ig = sigmoid_fast(g0);
            float fg = sigmoid_fast(g1);
            float gg = tanh_fast(g2);
            float og = sigmoid_fast(g3);
            c_reg = fg * c_reg + ig * gg;
            hnew  = og * tanh_fast(c_reg);
            g_hbuf[(t + 1) & 1][b][j] = hnew;
        }
        __syncthreads();
        if (tid == 0) st_rel(&g_flags[cta * FLAG_STRIDE], (unsigned)(t + 1));
        // off-critical-path archive store
        if (epi) g_hs[(t * B + lane) * H + j] = hnew;
    }
}

// ---------------- loss kernel: logits + logsumexp + NLL partials ----------------
__global__ void __launch_bounds__(256, 1)
loss_kernel(const int* __restrict__ ys,
            const float* __restrict__ W1,
            const float* __restrict__ b1)
{
    extern __shared__ float sm[];
    float* h_sm     = sm;                       // [PPC][1024]
    float* logit_sm = sm + PPC * 1024;          // [PPC][256]
    float* red      = logit_sm + PPC * 256;     // [PPC]

    const int tid  = threadIdx.x;
    const int pos0 = blockIdx.x * PPC;          // pos = t*B + b

    for (int idx4 = tid; idx4 < PPC * 1024 / 4; idx4 += 256) {
        int idx = idx4 * 4;
        *(float4*)&h_sm[idx] = *(const float4*)&g_hs[pos0 * 1024 + idx];
    }
    __syncthreads();

    ull acc2[PPC];
    #pragma unroll
    for (int p = 0; p < PPC; ++p) acc2[p] = 0ull;

    const ulonglong2* wrow = (const ulonglong2*)&W1[tid * 1024];
    for (int k4 = 0; k4 < 256; ++k4) {
        ulonglong2 w = __ldg(wrow + k4);
        #pragma unroll
        for (int p = 0; p < PPC; ++p) {
            ulonglong2 hv = *(const ulonglong2*)&h_sm[p * 1024 + k4 * 4];
            acc2[p] = fma2(w.x, hv.x, acc2[p]);
            acc2[p] = fma2(w.y, hv.y, acc2[p]);
        }
    }
    float bv = b1[tid];
    #pragma unroll
    for (int p = 0; p < PPC; ++p) {
        float2 f = unpk(acc2[p]);
        logit_sm[p * 256 + tid] = f.x + f.y + bv;
    }
    __syncthreads();

    const int wid = tid >> 5, lane = tid & 31;
    #pragma unroll
    for (int pp = 0; pp < 2; ++pp) {
        int p = wid * 2 + pp;
        const float* L = &logit_sm[p * 256];
        float vv[8];
        #pragma unroll
        for (int i = 0; i < 8; ++i) vv[i] = L[lane + 32 * i];
        float m = vv[0];
        #pragma unroll
        for (int i = 1; i < 8; ++i) m = fmaxf(m, vv[i]);
        for (int off = 16; off; off >>= 1)
            m = fmaxf(m, __shfl_xor_sync(0xffffffffu, m, off));
        float s = 0.0f;
        #pragma unroll
        for (int i = 0; i < 8; ++i) s += expf(vv[i] - m);
        for (int off = 16; off; off >>= 1)
            s += __shfl_xor_sync(0xffffffffu, s, off);
        if (lane == 0) {
            int pos = pos0 + p;                  // pos = t*B + b
            int b   = pos & 7;
            int t   = pos >> 3;
            int y   = __ldg(&ys[b * T + t]);
            float lse = m + logf(s);
            red[p] = lse - L[y];
        }
    }
    __syncthreads();
    if (tid == 0) {
        float ssum = 0.0f;
        #pragma unroll
        for (int p = 0; p < PPC; ++p) ssum += red[p];
        g_partials[blockIdx.x] = ssum;
    }
}

// ---------------- final reduction -> mean NLL ----------------
__global__ void final_kernel(float* __restrict__ out) {
    __shared__ float red[256];
    int tid = threadIdx.x;
    float s = 0.0f;
    for (int i = tid; i < LOSS_GRID; i += 256) s += g_partials[i];
    red[tid] = s;
    __syncthreads();
    for (int off = 128; off; off >>= 1) {
        if (tid < off) red[tid] += red[tid + off];
        __syncthreads();
    }
    if (tid == 0) out[0] = red[0] / (float)(B * T);
}

// ---------------- launch ----------------
extern "C" void kernel_launch(void* const* d_in, const int* in_sizes, int n_in,
                              void* d_out, int out_size)
{
    const int*   Xs   = (const int*)d_in[0];
    const int*   ys   = (const int*)d_in[1];
    /* d_in[2] = predict (always 0 here) */
    const float* W_ih = (const float*)d_in[3];
    const float* W_hh = (const float*)d_in[4];
    const float* b_ih = (const float*)d_in[5];
    const float* b_hh = (const float*)d_in[6];
    const float* W1   = (const float*)d_in[7];
    const float* b1   = (const float*)d_in[8];
    float* out = (float*)d_out;

    cudaFuncSetAttribute(loss_kernel, cudaFuncAttributeMaxDynamicSharedMemorySize,
                         LOSS_SMEM_BYTES);

    reset_kernel<<<1, 256>>>();
    lstm_kernel<<<GRID, NTHR>>>(Xs, W_ih, W_hh, b_ih, b_hh);
    loss_kernel<<<LOSS_GRID, 256, LOSS_SMEM_BYTES>>>(ys, W1, b1);
    final_kernel<<<1, 256>>>(out);
    (void)in_sizes; (void)n_in; (void)out_size;
}

// round 8
// speedup vs baseline: 1.0287x; 1.0287x over previous
#include <cuda_runtime.h>
#include <math.h>

#define B 8
#define T 2048
#define H 1024
#define V 256
#define GRID 128
#define NTHR 256
#define UPC 8            // hidden units per CTA (1 per warp)

typedef unsigned long long ull;

#define PPC 16           // positions per loss chunk
#define CHUNKS 8         // 128 positions per CTA
#define FLAG_STRIDE 8    // 32-byte padded flags

// dynamic smem: max(lstm: 32KB h + 1KB scr, loss: 64KB h + 16KB logits + red)
#define SMEM_DYN (PPC*1024*4 + PPC*256*4 + 64)

// ---------------- device scratch (static; no allocation) ----------------
__device__ float    g_hs[B * T * H];             // hidden states, layout [t][b][j]
__device__ float    g_hbuf[2][B][H];             // double-buffered h
__device__ unsigned g_flags[GRID * FLAG_STRIDE]; // monotonic per-CTA step counters
__device__ float    g_partials[GRID];            // per-CTA NLL partial sums
__device__ unsigned g_ticket;                    // monotonic arrival ticket

// ---------------- helpers ----------------
__device__ __forceinline__ ull fma2(ull a, ull b, ull c) {
    ull d;
    asm("fma.rn.f32x2 %0, %1, %2, %3;" : "=l"(d) : "l"(a), "l"(b), "l"(c));
    return d;
}
__device__ __forceinline__ float2 unpk(ull v) {
    float2 r;
    asm("mov.b64 {%0, %1}, %2;" : "=f"(r.x), "=f"(r.y) : "l"(v));
    return r;
}
__device__ __forceinline__ unsigned ld_cgv(const unsigned* p) {
    unsigned v;
    asm volatile("ld.global.cg.u32 %0, [%1];" : "=r"(v) : "l"(p));
    return v;
}
__device__ __forceinline__ void st_rel(unsigned* p, unsigned v) {
    asm volatile("st.release.gpu.global.u32 [%0], %1;" :: "l"(p), "r"(v) : "memory");
}
__device__ __forceinline__ void fence_acq() {
    asm volatile("fence.acq_rel.gpu;" ::: "memory");
}
__device__ __forceinline__ float tanh_fast(float x) {
    return 2.0f / (1.0f + __expf(-2.0f * x)) - 1.0f;
}
__device__ __forceinline__ float sigmoid_fast(float x) {
    return 1.0f / (1.0f + __expf(-x));
}

// ---------------- single fused persistent kernel ----------------
__global__ void __launch_bounds__(NTHR, 1)
charrnn_kernel(const int* __restrict__ Xs,
               const int* __restrict__ ys,
               const float* __restrict__ W_ih,
               const float* __restrict__ W_hh,
               const float* __restrict__ b_ih,
               const float* __restrict__ b_hh,
               const float* __restrict__ W1,
               const float* __restrict__ b1,
               float* __restrict__ out)
{
    extern __shared__ char smem[];
    float4* h4s    = (float4*)smem;                 // [B][256] f4, swizzled (32 KB)
    float*  scr    = (float*)(smem + 32768);        // [8][32] gate scratch
    __shared__ int s_win;

    const int tid  = threadIdx.x;
    const int wid  = tid >> 5;
    const int lane = tid & 31;
    const int j0   = blockIdx.x * UPC;
    const int j    = j0 + wid;
    const int cta  = blockIdx.x;

    // monotonic flag base (all flags equal at entry; read own)
    unsigned* myflag = &g_flags[cta * FLAG_STRIDE];
    const unsigned base = ld_cgv(myflag);

    // staging constants: this thread stages logical f4 col c for all b rows
    const int c    = wid * 32 + lane;               // warp w owns producers [16w,16w+16)
    const int dstc = (c >> 3) * 8 + (((c & 7) + (c >> 3)) & 7);
    const unsigned* pollflag = &g_flags[(wid * 16 + (lane & 15)) * FLAG_STRIDE];

    // ---- weights (once): 128 floats/thread in registers ----
    ull w2[4][16];
    #pragma unroll
    for (int g = 0; g < 4; ++g) {
        const ulonglong2* src =
            (const ulonglong2*)&W_hh[(g * H + j) * H + lane * 32];
        #pragma unroll
        for (int i = 0; i < 8; ++i) {
            ulonglong2 tt = src[i];
            w2[g][2*i]   = tt.x;
            w2[g][2*i+1] = tt.y;
        }
    }
    float bias0 = b_ih[0*H + j] + b_hh[0*H + j];
    float bias1 = b_ih[1*H + j] + b_hh[1*H + j];
    float bias2 = b_ih[2*H + j] + b_hh[2*H + j];
    float bias3 = b_ih[3*H + j] + b_hh[3*H + j];

    // zero h tile (t=0 uses h=0; no staging at t=0)
    for (int f = tid; f < B * 256; f += NTHR)
        h4s[f] = make_float4(0.f, 0.f, 0.f, 0.f);
    __syncthreads();

    float c_reg = 0.0f;

    // ================= recurrence =================
    for (int t = 0; t < T; ++t) {
        // prefetch input contribution (independent of h_t)
        float wi0 = 0.f, wi1 = 0.f, wi2 = 0.f, wi3 = 0.f;
        if (lane < 8) {
            int x = __ldg(&Xs[lane * T + t]);
            wi0 = __ldg(&W_ih[(0*H + j) * V + x]);
            wi1 = __ldg(&W_ih[(1*H + j) * V + x]);
            wi2 = __ldg(&W_ih[(2*H + j) * V + x]);
            wi3 = __ldg(&W_ih[(3*H + j) * V + x]);
        }

        if (t > 0) {
            // distributed wait: each warp polls its 16 producers (backoff)
            const unsigned tgt = base + (unsigned)t;
            if (lane < 16) {
                while (ld_cgv(pollflag) < tgt) { __nanosleep(32); }
            }
            __syncwarp();
            fence_acq();
            // stage this warp's producers' h columns (col c, all 8 b rows)
            const float4* hb = (const float4*)g_hbuf[t & 1];
            #pragma unroll
            for (int b2 = 0; b2 < B; ++b2)
                h4s[b2 * 256 + dstc] = __ldcg(hb + b2 * 256 + c);
        }
        __syncthreads();

        // gate partials: 512 FFMA2/thread
        float v[32];
        const ulonglong2* hbase = (const ulonglong2*)h4s + lane * 8;
        #pragma unroll
        for (int b = 0; b < B; ++b) {
            ull a0 = 0ull, a1 = 0ull, a2 = 0ull, a3 = 0ull;
            const ulonglong2* hrow = hbase + b * 256;
            #pragma unroll
            for (int i = 0; i < 8; ++i) {
                ulonglong2 hv = hrow[(i + lane) & 7];
                a0 = fma2(w2[0][2*i],   hv.x, a0);
                a1 = fma2(w2[1][2*i],   hv.x, a1);
                a2 = fma2(w2[2][2*i],   hv.x, a2);
                a3 = fma2(w2[3][2*i],   hv.x, a3);
                a0 = fma2(w2[0][2*i+1], hv.y, a0);
                a1 = fma2(w2[1][2*i+1], hv.y, a1);
                a2 = fma2(w2[2][2*i+1], hv.y, a2);
                a3 = fma2(w2[3][2*i+1], hv.y, a3);
            }
            float2 f0 = unpk(a0), f1 = unpk(a1), f2 = unpk(a2), f3 = unpk(a3);
            v[0*8 + b] = f0.x + f0.y;
            v[1*8 + b] = f1.x + f1.y;
            v[2*8 + b] = f2.x + f2.y;
            v[3*8 + b] = f3.x + f3.y;
        }

        // multi-value butterfly over 32 lanes
        #pragma unroll
        for (int s = 0; s < 5; ++s) {
            const int m   = 1 << s;
            const int cnt = 16 >> s;
            const bool up = (lane & m) != 0;
            #pragma unroll
            for (int i = 0; i < cnt; ++i) {
                float send = up ? v[i] : v[i + cnt];
                float recv = __shfl_xor_sync(0xffffffffu, send, m);
                float keep = up ? v[i + cnt] : v[i];
                v[i] = keep + recv;
            }
        }
        {
            int o = (int)(__brev((unsigned)lane) >> 27);   // o = g*8 + b
            scr[wid * 32 + o] = v[0];
        }
        __syncwarp();

        float hnew = 0.0f;
        if (lane < 8) {
            const int b = lane;
            float g0 = scr[wid*32 + 0*8 + b] + wi0 + bias0;
            float g1 = scr[wid*32 + 1*8 + b] + wi1 + bias1;
            float g2 = scr[wid*32 + 2*8 + b] + wi2 + bias2;
            float g3 = scr[wid*32 + 3*8 + b] + wi3 + bias3;
            float ig = sigmoid_fast(g0);
            float fg = sigmoid_fast(g1);
            float gg = tanh_fast(g2);
            float og = sigmoid_fast(g3);
            c_reg = fg * c_reg + ig * gg;
            hnew  = og * tanh_fast(c_reg);
            g_hbuf[(t + 1) & 1][b][j] = hnew;
        }
        __syncthreads();
        if (tid == 0) st_rel(myflag, base + (unsigned)(t + 1));
        // off-critical-path archive store
        if (lane < 8) g_hs[(t * B + lane) * H + j] = hnew;
    }

    // ---- publish archives, wait for all CTAs ----
    __threadfence();
    __syncthreads();
    if (tid == 0) st_rel(myflag, base + (unsigned)(T + 1));
    {
        const unsigned tgt = base + (unsigned)(T + 1);
        if (lane < 16) {
            while (ld_cgv(pollflag) < tgt) { __nanosleep(64); }
        }
        __syncwarp();
        fence_acq();
    }
    __syncthreads();
    fence_acq();

    // ================= loss phase: 128 positions per CTA =================
    float* h_sm     = (float*)smem;                     // [PPC][1024]
    float* logit_sm = (float*)(smem + PPC*1024*4);      // [PPC][256]
    float* redp     = (float*)(smem + PPC*1024*4 + PPC*256*4);  // [PPC]

    float cta_sum = 0.0f;   // accumulated by tid 0

    for (int chunk = 0; chunk < CHUNKS; ++chunk) {
        const int pos0 = cta * 128 + chunk * PPC;       // pos = t*B + b

        for (int idx4 = tid; idx4 < PPC * 1024 / 4; idx4 += NTHR) {
            *(float4*)&h_sm[idx4 * 4] =
                __ldcg((const float4*)&g_hs[pos0 * 1024] + idx4);
        }
        __syncthreads();

        ull acc2[PPC];
        #pragma unroll
        for (int p = 0; p < PPC; ++p) acc2[p] = 0ull;

        const ulonglong2* wrow = (const ulonglong2*)&W1[tid * 1024];
        for (int k4 = 0; k4 < 256; ++k4) {
            ulonglong2 w = __ldg(wrow + k4);
            #pragma unroll
            for (int p = 0; p < PPC; ++p) {
                ulonglong2 hv = *(const ulonglong2*)&h_sm[p * 1024 + k4 * 4];
                acc2[p] = fma2(w.x, hv.x, acc2[p]);
                acc2[p] = fma2(w.y, hv.y, acc2[p]);
            }
        }
        float bv = b1[tid];
        #pragma unroll
        for (int p = 0; p < PPC; ++p) {
            float2 f = unpk(acc2[p]);
            logit_sm[p * 256 + tid] = f.x + f.y + bv;
        }
        __syncthreads();

        #pragma unroll
        for (int pp = 0; pp < 2; ++pp) {
            int p = wid * 2 + pp;
            const float* L = &logit_sm[p * 256];
            float vv[8];
            #pragma unroll
            for (int i = 0; i < 8; ++i) vv[i] = L[lane + 32 * i];
            float m = vv[0];
            #pragma unroll
            for (int i = 1; i < 8; ++i) m = fmaxf(m, vv[i]);
            for (int off = 16; off; off >>= 1)
                m = fmaxf(m, __shfl_xor_sync(0xffffffffu, m, off));
            float s = 0.0f;
            #pragma unroll
            for (int i = 0; i < 8; ++i) s += expf(vv[i] - m);
            for (int off = 16; off; off >>= 1)
                s += __shfl_xor_sync(0xffffffffu, s, off);
            if (lane == 0) {
                int pos = pos0 + p;                  // pos = t*B + b
                int b   = pos & 7;
                int t   = pos >> 3;
                int y   = __ldg(&ys[b * T + t]);
                redp[p] = (m + logf(s)) - L[y];
            }
        }
        __syncthreads();
        if (tid == 0) {
            float ssum = 0.0f;
            #pragma unroll
            for (int p = 0; p < PPC; ++p) ssum += redp[p];
            cta_sum += ssum;
        }
        __syncthreads();   // redp/h_sm free for next chunk
    }

    // ---- deterministic final reduction by the last-arriving CTA ----
    if (tid == 0) {
        g_partials[cta] = cta_sum;
        __threadfence();
        unsigned old = atomicAdd(&g_ticket, 1u);
        s_win = ((old % GRID) == (GRID - 1)) ? 1 : 0;
    }
    __syncthreads();
    if (s_win) {
        __threadfence();
        float* r2 = (float*)smem;
        float s = (tid < GRID) ? __ldcg(&g_partials[tid]) : 0.0f;
        r2[tid] = s;
        __syncthreads();
        for (int off = 128; off; off >>= 1) {
            if (tid < off) r2[tid] += r2[tid + off];
            __syncthreads();
        }
        if (tid == 0) out[0] = r2[0] / (float)(B * T);
    }
}

// ---------------- launch ----------------
extern "C" void kernel_launch(void* const* d_in, const int* in_sizes, int n_in,
                              void* d_out, int out_size)
{
    const int*   Xs   = (const int*)d_in[0];
    const int*   ys   = (const int*)d_in[1];
    /* d_in[2] = predict (always 0 here) */
    const float* W_ih = (const float*)d_in[3];
    const float* W_hh = (const float*)d_in[4];
    const float* b_ih = (const float*)d_in[5];
    const float* b_hh = (const float*)d_in[6];
    const float* W1   = (const float*)d_in[7];
    const float* b1   = (const float*)d_in[8];
    float* out = (float*)d_out;

    cudaFuncSetAttribute(charrnn_kernel,
                         cudaFuncAttributeMaxDynamicSharedMemorySize, SMEM_DYN);

    charrnn_kernel<<<GRID, NTHR, SMEM_DYN>>>(Xs, ys, W_ih, W_hh, b_ih, b_hh,
                                             W1, b1, out);
    (void)in_sizes; (void)n_in; (void)out_size;
}

// round 9
// speedup vs baseline: 1.2784x; 1.2427x over previous
#include <cuda_runtime.h>
#include <math.h>

#define B 8
#define T 2048
#define H 1024
#define V 256
#define GRID 128
#define NTHR 256
#define UPC 8            // hidden units per CTA (1 per warp)

typedef unsigned long long ull;

#define PPC 16           // positions per loss chunk
#define CHUNKS 8         // 128 positions per CTA
#define FLAG_STRIDE 8    // 32-byte padded flags

// dynamic smem: max(lstm: 32KB h + 1KB scr, loss: 64KB h + 16KB logits + red)
#define SMEM_DYN (PPC*1024*4 + PPC*256*4 + 64)

// ---------------- device scratch (static; no allocation) ----------------
__device__ float    g_hs[B * T * H];             // hidden states, layout [t][b][j]
__device__ float    g_hbuf[2][B][H];             // double-buffered h
__device__ unsigned g_flags[GRID * FLAG_STRIDE]; // monotonic per-CTA step counters
__device__ float    g_partials[GRID];            // per-CTA NLL partial sums
__device__ unsigned g_ticket;                    // monotonic arrival ticket

// ---------------- helpers ----------------
__device__ __forceinline__ ull fma2(ull a, ull b, ull c) {
    ull d;
    asm("fma.rn.f32x2 %0, %1, %2, %3;" : "=l"(d) : "l"(a), "l"(b), "l"(c));
    return d;
}
__device__ __forceinline__ float2 unpk(ull v) {
    float2 r;
    asm("mov.b64 {%0, %1}, %2;" : "=f"(r.x), "=f"(r.y) : "l"(v));
    return r;
}
__device__ __forceinline__ unsigned ld_cgv(const unsigned* p) {
    unsigned v;
    asm volatile("ld.global.cg.u32 %0, [%1];" : "=r"(v) : "l"(p));
    return v;
}
__device__ __forceinline__ void st_rel(unsigned* p, unsigned v) {
    asm volatile("st.release.gpu.global.u32 [%0], %1;" :: "l"(p), "r"(v) : "memory");
}
__device__ __forceinline__ void fence_acq() {
    asm volatile("fence.acq_rel.gpu;" ::: "memory");
}
__device__ __forceinline__ float tanh_fast(float x) {
    return 2.0f / (1.0f + __expf(-2.0f * x)) - 1.0f;
}
__device__ __forceinline__ float sigmoid_fast(float x) {
    return 1.0f / (1.0f + __expf(-x));
}

// ---------------- single fused persistent kernel ----------------
__global__ void __launch_bounds__(NTHR, 1)
charrnn_kernel(const int* __restrict__ Xs,
               const int* __restrict__ ys,
               const float* __restrict__ W_ih,
               const float* __restrict__ W_hh,
               const float* __restrict__ b_ih,
               const float* __restrict__ b_hh,
               const float* __restrict__ W1,
               const float* __restrict__ b1,
               float* __restrict__ out)
{
    extern __shared__ char smem[];
    float4* h4s = (float4*)smem;                 // [B][256] f4, swizzled (32 KB)
    float*  scr = (float*)(smem + 32768);        // [8][32] gate scratch
    __shared__ int s_win;

    const int tid  = threadIdx.x;
    const int wid  = tid >> 5;
    const int lane = tid & 31;
    const int j0   = blockIdx.x * UPC;
    const int j    = j0 + wid;
    const int cta  = blockIdx.x;

    // monotonic flag base (all flags equal at entry; read own)
    unsigned* myflag = &g_flags[cta * FLAG_STRIDE];
    const unsigned base = ld_cgv(myflag);

    // warp-0 poll targets (R5 scheme: 4 flags per lane, padded)
    const unsigned* fl0 = &g_flags[(lane)      * FLAG_STRIDE];
    const unsigned* fl1 = &g_flags[(lane + 32) * FLAG_STRIDE];
    const unsigned* fl2 = &g_flags[(lane + 64) * FLAG_STRIDE];
    const unsigned* fl3 = &g_flags[(lane + 96) * FLAG_STRIDE];

    // ---- weights (once): 128 floats/thread in registers ----
    ull w2[4][16];
    #pragma unroll
    for (int g = 0; g < 4; ++g) {
        const ulonglong2* src =
            (const ulonglong2*)&W_hh[(g * H + j) * H + lane * 32];
        #pragma unroll
        for (int i = 0; i < 8; ++i) {
            ulonglong2 tt = src[i];
            w2[g][2*i]   = tt.x;
            w2[g][2*i+1] = tt.y;
        }
    }
    float bias0 = b_ih[0*H + j] + b_hh[0*H + j];
    float bias1 = b_ih[1*H + j] + b_hh[1*H + j];
    float bias2 = b_ih[2*H + j] + b_hh[2*H + j];
    float bias3 = b_ih[3*H + j] + b_hh[3*H + j];

    // zero h tile (t=0 uses h=0; no staging at t=0)
    for (int f = tid; f < B * 256; f += NTHR)
        h4s[f] = make_float4(0.f, 0.f, 0.f, 0.f);
    __syncthreads();

    float c_reg = 0.0f;

    // ================= recurrence =================
    for (int t = 0; t < T; ++t) {
        // prefetch input contribution (independent of h_t)
        float wi0 = 0.f, wi1 = 0.f, wi2 = 0.f, wi3 = 0.f;
        if (lane < 8) {
            int x = __ldg(&Xs[lane * T + t]);
            wi0 = __ldg(&W_ih[(0*H + j) * V + x]);
            wi1 = __ldg(&W_ih[(1*H + j) * V + x]);
            wi2 = __ldg(&W_ih[(2*H + j) * V + x]);
            wi3 = __ldg(&W_ih[(3*H + j) * V + x]);
        }

        if (t > 0) {
            // wait: warp 0 hot-spins on all 128 flags (4 per lane)
            if (wid == 0) {
                const unsigned tgt = base + (unsigned)t;
                bool d0 = false, d1 = false, d2 = false, d3 = false;
                while (true) {
                    if (!d0) d0 = ld_cgv(fl0) >= tgt;
                    if (!d1) d1 = ld_cgv(fl1) >= tgt;
                    if (!d2) d2 = ld_cgv(fl2) >= tgt;
                    if (!d3) d3 = ld_cgv(fl3) >= tgt;
                    if (__all_sync(0xffffffffu, d0 && d1 && d2 && d3)) break;
                }
                fence_acq();
            }
            __syncthreads();
            // stage h_t into swizzled SMEM, CTA-wide coalesced
            const float4* hb = (const float4*)g_hbuf[t & 1];
            #pragma unroll
            for (int f = tid; f < B * 256; f += NTHR) {
                int b2 = f >> 8;
                int l2 = (f >> 3) & 31;
                int i2 = f & 7;
                float4 vv = __ldcg(hb + f);
                h4s[b2 * 256 + l2 * 8 + ((i2 + l2) & 7)] = vv;
            }
            __syncthreads();
        }

        // gate partials: 512 FFMA2/thread
        float v[32];
        const ulonglong2* hbase = (const ulonglong2*)h4s + lane * 8;
        #pragma unroll
        for (int b = 0; b < B; ++b) {
            ull a0 = 0ull, a1 = 0ull, a2 = 0ull, a3 = 0ull;
            const ulonglong2* hrow = hbase + b * 256;
            #pragma unroll
            for (int i = 0; i < 8; ++i) {
                ulonglong2 hv = hrow[(i + lane) & 7];
                a0 = fma2(w2[0][2*i],   hv.x, a0);
                a1 = fma2(w2[1][2*i],   hv.x, a1);
                a2 = fma2(w2[2][2*i],   hv.x, a2);
                a3 = fma2(w2[3][2*i],   hv.x, a3);
                a0 = fma2(w2[0][2*i+1], hv.y, a0);
                a1 = fma2(w2[1][2*i+1], hv.y, a1);
                a2 = fma2(w2[2][2*i+1], hv.y, a2);
                a3 = fma2(w2[3][2*i+1], hv.y, a3);
            }
            float2 f0 = unpk(a0), f1 = unpk(a1), f2 = unpk(a2), f3 = unpk(a3);
            v[0*8 + b] = f0.x + f0.y;
            v[1*8 + b] = f1.x + f1.y;
            v[2*8 + b] = f2.x + f2.y;
            v[3*8 + b] = f3.x + f3.y;
        }

        // multi-value butterfly over 32 lanes
        #pragma unroll
        for (int s = 0; s < 5; ++s) {
            const int m   = 1 << s;
            const int cnt = 16 >> s;
            const bool up = (lane & m) != 0;
            #pragma unroll
            for (int i = 0; i < cnt; ++i) {
                float send = up ? v[i] : v[i + cnt];
                float recv = __shfl_xor_sync(0xffffffffu, send, m);
                float keep = up ? v[i + cnt] : v[i];
                v[i] = keep + recv;
            }
        }
        {
            int o = (int)(__brev((unsigned)lane) >> 27);   // o = g*8 + b
            scr[wid * 32 + o] = v[0];
        }
        __syncwarp();

        float hnew = 0.0f;
        if (lane < 8) {
            const int b = lane;
            float g0 = scr[wid*32 + 0*8 + b] + wi0 + bias0;
            float g1 = scr[wid*32 + 1*8 + b] + wi1 + bias1;
            float g2 = scr[wid*32 + 2*8 + b] + wi2 + bias2;
            float g3 = scr[wid*32 + 3*8 + b] + wi3 + bias3;
            float ig = sigmoid_fast(g0);
            float fg = sigmoid_fast(g1);
            float gg = tanh_fast(g2);
            float og = sigmoid_fast(g3);
            c_reg = fg * c_reg + ig * gg;
            hnew  = og * tanh_fast(c_reg);
            g_hbuf[(t + 1) & 1][b][j] = hnew;
        }
        __syncthreads();
        if (tid == 0) st_rel(myflag, base + (unsigned)(t + 1));
        // off-critical-path archive store
        if (lane < 8) g_hs[(t * B + lane) * H + j] = hnew;
    }

    // ---- publish archives, wait for all CTAs ----
    __threadfence();
    __syncthreads();
    if (tid == 0) st_rel(myflag, base + (unsigned)(T + 1));
    if (wid == 0) {
        const unsigned tgt = base + (unsigned)(T + 1);
        bool d0 = false, d1 = false, d2 = false, d3 = false;
        while (true) {
            if (!d0) d0 = ld_cgv(fl0) >= tgt;
            if (!d1) d1 = ld_cgv(fl1) >= tgt;
            if (!d2) d2 = ld_cgv(fl2) >= tgt;
            if (!d3) d3 = ld_cgv(fl3) >= tgt;
            if (__all_sync(0xffffffffu, d0 && d1 && d2 && d3)) break;
            __nanosleep(64);
        }
        fence_acq();
    }
    __syncthreads();

    // ================= loss phase: 128 positions per CTA =================
    float* h_sm     = (float*)smem;                     // [PPC][1024]
    float* logit_sm = (float*)(smem + PPC*1024*4);      // [PPC][256]
    float* redp     = (float*)(smem + PPC*1024*4 + PPC*256*4);  // [PPC]

    float cta_sum = 0.0f;   // accumulated by tid 0

    for (int chunk = 0; chunk < CHUNKS; ++chunk) {
        const int pos0 = cta * 128 + chunk * PPC;       // pos = t*B + b

        for (int idx4 = tid; idx4 < PPC * 1024 / 4; idx4 += NTHR) {
            *(float4*)&h_sm[idx4 * 4] =
                __ldcg((const float4*)&g_hs[pos0 * 1024] + idx4);
        }
        __syncthreads();

        ull acc2[PPC];
        #pragma unroll
        for (int p = 0; p < PPC; ++p) acc2[p] = 0ull;

        const ulonglong2* wrow = (const ulonglong2*)&W1[tid * 1024];
        for (int k4 = 0; k4 < 256; ++k4) {
            ulonglong2 w = __ldg(wrow + k4);
            #pragma unroll
            for (int p = 0; p < PPC; ++p) {
                ulonglong2 hv = *(const ulonglong2*)&h_sm[p * 1024 + k4 * 4];
                acc2[p] = fma2(w.x, hv.x, acc2[p]);
                acc2[p] = fma2(w.y, hv.y, acc2[p]);
            }
        }
        float bv = b1[tid];
        #pragma unroll
        for (int p = 0; p < PPC; ++p) {
            float2 f = unpk(acc2[p]);
            logit_sm[p * 256 + tid] = f.x + f.y + bv;
        }
        __syncthreads();

        #pragma unroll
        for (int pp = 0; pp < 2; ++pp) {
            int p = wid * 2 + pp;
            const float* L = &logit_sm[p * 256];
            float vv[8];
            #pragma unroll
            for (int i = 0; i < 8; ++i) vv[i] = L[lane + 32 * i];
            float m = vv[0];
            #pragma unroll
            for (int i = 1; i < 8; ++i) m = fmaxf(m, vv[i]);
            for (int off = 16; off; off >>= 1)
                m = fmaxf(m, __shfl_xor_sync(0xffffffffu, m, off));
            float s = 0.0f;
            #pragma unroll
            for (int i = 0; i < 8; ++i) s += expf(vv[i] - m);
            for (int off = 16; off; off >>= 1)
                s += __shfl_xor_sync(0xffffffffu, s, off);
            if (lane == 0) {
                int pos = pos0 + p;                  // pos = t*B + b
                int b   = pos & 7;
                int t   = pos >> 3;
                int y   = __ldg(&ys[b * T + t]);
                redp[p] = (m + logf(s)) - L[y];
            }
        }
        __syncthreads();
        if (tid == 0) {
            float ssum = 0.0f;
            #pragma unroll
            for (int p = 0; p < PPC; ++p) ssum += redp[p];
            cta_sum += ssum;
        }
        __syncthreads();   // redp/h_sm free for next chunk
    }

    // ---- deterministic final reduction by the last-arriving CTA ----
    if (tid == 0) {
        g_partials[cta] = cta_sum;
        __threadfence();
        unsigned old = atomicAdd(&g_ticket, 1u);
        s_win = ((old % GRID) == (GRID - 1)) ? 1 : 0;
    }
    __syncthreads();
    if (s_win) {
        __threadfence();
        float* r2 = (float*)smem;
        float s = (tid < GRID) ? __ldcg(&g_partials[tid]) : 0.0f;
        r2[tid] = s;
        __syncthreads();
        for (int off = 128; off; off >>= 1) {
            if (tid < off) r2[tid] += r2[tid + off];
            __syncthreads();
        }
        if (tid == 0) out[0] = r2[0] / (float)(B * T);
    }
}

// ---------------- launch ----------------
extern "C" void kernel_launch(void* const* d_in, const int* in_sizes, int n_in,
                              void* d_out, int out_size)
{
    const int*   Xs   = (const int*)d_in[0];
    const int*   ys   = (const int*)d_in[1];
    /* d_in[2] = predict (always 0 here) */
    const float* W_ih = (const float*)d_in[3];
    const float* W_hh = (const float*)d_in[4];
    const float* b_ih = (const float*)d_in[5];
    const float* b_hh = (const float*)d_in[6];
    const float* W1   = (const float*)d_in[7];
    const float* b1   = (const float*)d_in[8];
    float* out = (float*)d_out;

    cudaFuncSetAttribute(charrnn_kernel,
                         cudaFuncAttributeMaxDynamicSharedMemorySize, SMEM_DYN);

    charrnn_kernel<<<GRID, NTHR, SMEM_DYN>>>(Xs, ys, W_ih, W_hh, b_ih, b_hh,
                                             W1, b1, out);
    (void)in_sizes; (void)n_in; (void)out_size;
}

// round 11
// speedup vs baseline: 1.6619x; 1.3001x over previous
#include <cuda_runtime.h>
#include <math.h>

#define B 8
#define T 2048
#define H 1024
#define V 256
#define GRID 128
#define NTHR 256
#define UPC 8            // hidden units per CTA

typedef unsigned long long ull;

#define PPC 16           // positions per loss chunk
#define CHUNKS 8         // 128 positions per CTA
#define FLAG_STRIDE 8    // 32-byte padded flags

// lstm-phase SMEM: h_s[8][1028] f32 (32896B) | part[8][292] f32 (9344B) | bias[32]
#define PH_HS    0
#define PH_PART  32896
#define PH_BIAS  42240
// loss-phase SMEM: h[PPC][1024] | logits[PPC][256] | red[PPC]
#define SMEM_DYN (PPC*1024*4 + PPC*256*4 + 64)

// ---------------- device scratch (static; no allocation) ----------------
__device__ float    g_hs[B * T * H];             // hidden states, [t][b][j]
__device__ float    g_hbuf[2][B][H];             // double-buffered h
__device__ unsigned g_flags[GRID * FLAG_STRIDE]; // monotonic per-CTA counters
__device__ float    g_partials[GRID];
__device__ unsigned g_ticket;

// ---------------- helpers ----------------
__device__ __forceinline__ ull fma2(ull a, ull b, ull c) {
    ull d;
    asm("fma.rn.f32x2 %0, %1, %2, %3;" : "=l"(d) : "l"(a), "l"(b), "l"(c));
    return d;
}
__device__ __forceinline__ float2 unpk(ull v) {
    float2 r;
    asm("mov.b64 {%0, %1}, %2;" : "=f"(r.x), "=f"(r.y) : "l"(v));
    return r;
}
__device__ __forceinline__ unsigned ld_cgv(const unsigned* p) {
    unsigned v;
    asm volatile("ld.global.cg.u32 %0, [%1];" : "=r"(v) : "l"(p));
    return v;
}
__device__ __forceinline__ void st_rel(unsigned* p, unsigned v) {
    asm volatile("st.release.gpu.global.u32 [%0], %1;" :: "l"(p), "r"(v) : "memory");
}
__device__ __forceinline__ void fence_acq() {
    asm volatile("fence.acq_rel.gpu;" ::: "memory");
}
__device__ __forceinline__ float tanh_fast(float x) {
    return 2.0f / (1.0f + __expf(-2.0f * x)) - 1.0f;
}
__device__ __forceinline__ float sigmoid_fast(float x) {
    return 1.0f / (1.0f + __expf(-x));
}
__device__ __forceinline__ unsigned f2tf32(float f) {
    unsigned r;
    asm("cvt.rna.tf32.f32 %0, %1;" : "=r"(r) : "f"(f));
    return r;
}
// m16n8k8 tf32 MMA, fp32 accumulate (warp-wide, sm_80+)
__device__ __forceinline__ void mma_tf32(float* d, const unsigned* a,
                                         unsigned b0, unsigned b1) {
    asm volatile(
        "mma.sync.aligned.m16n8k8.row.col.f32.tf32.tf32.f32 "
        "{%0,%1,%2,%3}, {%4,%5,%6,%7}, {%8,%9}, {%0,%1,%2,%3};"
        : "+f"(d[0]), "+f"(d[1]), "+f"(d[2]), "+f"(d[3])
        : "r"(a[0]), "r"(a[1]), "r"(a[2]), "r"(a[3]), "r"(b0), "r"(b1));
}

// ---------------- single fused persistent kernel ----------------
__global__ void __launch_bounds__(NTHR, 1)
charrnn_kernel(const int* __restrict__ Xs,
               const int* __restrict__ ys,
               const float* __restrict__ W_ih,
               const float* __restrict__ W_hh,
               const float* __restrict__ b_ih,
               const float* __restrict__ b_hh,
               const float* __restrict__ W1,
               const float* __restrict__ b1,
               float* __restrict__ out)
{
    extern __shared__ char smem[];
    float* h_s    = (float*)(smem + PH_HS);      // [8][1028]
    float* part   = (float*)(smem + PH_PART);    // [8][292] (32 rows x 9 + pad)
    float* bias_s = (float*)(smem + PH_BIAS);    // [32] (g*8+u)
    __shared__ int s_win;

    const int tid  = threadIdx.x;
    const int wid  = tid >> 5;
    const int lane = tid & 31;
    const int cta  = blockIdx.x;
    const int j0   = cta * UPC;

    // monotonic flag base
    unsigned* myflag = &g_flags[cta * FLAG_STRIDE];
    const unsigned fbase = ld_cgv(myflag);
    const unsigned* fl0 = &g_flags[(lane)      * FLAG_STRIDE];
    const unsigned* fl1 = &g_flags[(lane + 32) * FLAG_STRIDE];
    const unsigned* fl2 = &g_flags[(lane + 64) * FLAG_STRIDE];
    const unsigned* fl3 = &g_flags[(lane + 96) * FLAG_STRIDE];

    // ---- A fragments (once): warp wid owns K-slice [wid*128, wid*128+128)
    // row r = g*8 + u (0..31); 2 M-tiles of 16 rows; tf32 in registers.
    unsigned wA[2][16][4];   // 128 regs
    {
        const int ks = wid * 128;
        const int rlo = lane >> 2;          // row within tile
        const int kc  = lane & 3;           // k within quad
        #pragma unroll
        for (int m = 0; m < 2; ++m) {
            #pragma unroll
            for (int k8 = 0; k8 < 16; ++k8) {
                int r0 = m * 16 + rlo;
                int r1 = r0 + 8;
                int kk = ks + k8 * 8 + kc;
                int g0 = r0 >> 3, u0g = r0 & 7;
                int g1 = r1 >> 3, u1g = r1 & 7;
                const float* row0 = &W_hh[(g0 * H + j0 + u0g) * H];
                const float* row1 = &W_hh[(g1 * H + j0 + u1g) * H];
                wA[m][k8][0] = f2tf32(row0[kk]);
                wA[m][k8][1] = f2tf32(row1[kk]);
                wA[m][k8][2] = f2tf32(row0[kk + 4]);
                wA[m][k8][3] = f2tf32(row1[kk + 4]);
            }
        }
    }
    if (tid < 32) {
        int g = tid >> 3, u = tid & 7;
        bias_s[tid] = b_ih[g * H + j0 + u] + b_hh[g * H + j0 + u];
    }
    // zero h tile (t=0 uses h=0)
    for (int i = tid; i < 8 * 1028; i += NTHR) h_s[i] = 0.0f;
    __syncthreads();

    // epilogue constants: thread tid<64 owns cell (u = tid&7, b = tid>>3)
    const int eu = tid & 7, eb = tid >> 3;
    const int ej = j0 + eu;
    float c_reg = 0.0f;

    // B-fragment base: col n = lane>>2 (batch), k = ks + lane&3
    const float* hB = &h_s[(lane >> 2) * 1028 + wid * 128 + (lane & 3)];
    float* pw = &part[wid * 292];
    const int prow = lane >> 2, pcol = 2 * (lane & 3);

    // ================= recurrence =================
    for (int t = 0; t < T; ++t) {
        // prefetch input contribution (independent of h_t)
        float wi0 = 0.f, wi1 = 0.f, wi2 = 0.f, wi3 = 0.f;
        if (tid < 64) {
            int x = __ldg(&Xs[eb * T + t]);
            wi0 = __ldg(&W_ih[(0*H + ej) * V + x]);
            wi1 = __ldg(&W_ih[(1*H + ej) * V + x]);
            wi2 = __ldg(&W_ih[(2*H + ej) * V + x]);
            wi3 = __ldg(&W_ih[(3*H + ej) * V + x]);
        }

        if (t > 0) {
            // wait: warp 0 hot-spins on all 128 flags (4 per lane)
            if (wid == 0) {
                const unsigned tgt = fbase + (unsigned)t;
                bool d0 = false, d1 = false, d2 = false, d3 = false;
                while (true) {
                    if (!d0) d0 = ld_cgv(fl0) >= tgt;
                    if (!d1) d1 = ld_cgv(fl1) >= tgt;
                    if (!d2) d2 = ld_cgv(fl2) >= tgt;
                    if (!d3) d3 = ld_cgv(fl3) >= tgt;
                    if (__all_sync(0xffffffffu, d0 && d1 && d2 && d3)) break;
                }
                fence_acq();
            }
            __syncthreads();
            // stage h_t into padded SMEM [b][1028]
            const float4* hb = (const float4*)g_hbuf[t & 1];
            #pragma unroll
            for (int f = tid; f < 2048; f += NTHR) {
                int b2 = f >> 8, k4 = f & 255;
                *(float4*)&h_s[b2 * 1028 + k4 * 4] = __ldcg(hb + f);
            }
            __syncthreads();
        }

        // ---- tensor-core gate matmul: 32 HMMA per warp ----
        float d0[4] = {0.f, 0.f, 0.f, 0.f};
        float d1[4] = {0.f, 0.f, 0.f, 0.f};
        #pragma unroll
        for (int k8 = 0; k8 < 16; ++k8) {
            float bf0 = hB[k8 * 8];
            float bf1 = hB[k8 * 8 + 4];
            unsigned b0 = f2tf32(bf0), b1 = f2tf32(bf1);
            mma_tf32(d0, wA[0][k8], b0, b1);
            mma_tf32(d1, wA[1][k8], b0, b1);
        }
        // store per-warp partials: part[w][row*9 + col]
        pw[(prow     ) * 9 + pcol    ] = d0[0];
        pw[(prow     ) * 9 + pcol + 1] = d0[1];
        pw[(prow +  8) * 9 + pcol    ] = d0[2];
        pw[(prow +  8) * 9 + pcol + 1] = d0[3];
        pw[(prow + 16) * 9 + pcol    ] = d1[0];
        pw[(prow + 16) * 9 + pcol + 1] = d1[1];
        pw[(prow + 24) * 9 + pcol    ] = d1[2];
        pw[(prow + 24) * 9 + pcol + 1] = d1[3];
        __syncthreads();

        // ---- epilogue: 64 cells (u, b); sum K-slices across 8 warps ----
        float hnew = 0.0f;
        if (tid < 64) {
            float S0 = 0.f, S1 = 0.f, S2 = 0.f, S3 = 0.f;
            #pragma unroll
            for (int w = 0; w < 8; ++w) {
                const float* pp = &part[w * 292];
                S0 += pp[(0*8 + eu) * 9 + eb];
                S1 += pp[(1*8 + eu) * 9 + eb];
                S2 += pp[(2*8 + eu) * 9 + eb];
                S3 += pp[(3*8 + eu) * 9 + eb];
            }
            S0 += wi0 + bias_s[0*8 + eu];
            S1 += wi1 + bias_s[1*8 + eu];
            S2 += wi2 + bias_s[2*8 + eu];
            S3 += wi3 + bias_s[3*8 + eu];
            float ig = sigmoid_fast(S0);
            float fg = sigmoid_fast(S1);
            float gg = tanh_fast(S2);
            float og = sigmoid_fast(S3);
            c_reg = fg * c_reg + ig * gg;
            hnew  = og * tanh_fast(c_reg);
            g_hbuf[(t + 1) & 1][eb][ej] = hnew;
        }
        __syncthreads();
        if (tid == 0) st_rel(myflag, fbase + (unsigned)(t + 1));
        // off-critical-path archive
        if (tid < 64) g_hs[(t * B + eb) * H + ej] = hnew;
    }

    // ---- publish archives; wait for all CTAs ----
    __threadfence();
    __syncthreads();
    if (tid == 0) st_rel(myflag, fbase + (unsigned)(T + 1));
    if (wid == 0) {
        const unsigned tgt = fbase + (unsigned)(T + 1);
        bool d0 = false, d1 = false, d2 = false, d3 = false;
        while (true) {
            if (!d0) d0 = ld_cgv(fl0) >= tgt;
            if (!d1) d1 = ld_cgv(fl1) >= tgt;
            if (!d2) d2 = ld_cgv(fl2) >= tgt;
            if (!d3) d3 = ld_cgv(fl3) >= tgt;
            if (__all_sync(0xffffffffu, d0 && d1 && d2 && d3)) break;
            __nanosleep(64);
        }
        fence_acq();
    }
    __syncthreads();

    // ================= loss phase: 128 positions per CTA =================
    float* h_sm     = (float*)smem;                              // [PPC][1024]
    float* logit_sm = (float*)(smem + PPC*1024*4);               // [PPC][256]
    float* redp     = (float*)(smem + PPC*1024*4 + PPC*256*4);   // [PPC]

    float cta_sum = 0.0f;

    for (int chunk = 0; chunk < CHUNKS; ++chunk) {
        const int pos0 = cta * 128 + chunk * PPC;                // pos = t*B + b

        for (int idx4 = tid; idx4 < PPC * 1024 / 4; idx4 += NTHR) {
            *(float4*)&h_sm[idx4 * 4] =
                __ldcg((const float4*)&g_hs[pos0 * 1024] + idx4);
        }
        __syncthreads();

        ull acc2[PPC];
        #pragma unroll
        for (int p = 0; p < PPC; ++p) acc2[p] = 0ull;

        const ulonglong2* wrow = (const ulonglong2*)&W1[tid * 1024];
        for (int k4 = 0; k4 < 256; ++k4) {
            ulonglong2 w = __ldg(wrow + k4);
            #pragma unroll
            for (int p = 0; p < PPC; ++p) {
                ulonglong2 hv = *(const ulonglong2*)&h_sm[p * 1024 + k4 * 4];
                acc2[p] = fma2(w.x, hv.x, acc2[p]);
                acc2[p] = fma2(w.y, hv.y, acc2[p]);
            }
        }
        float bv = b1[tid];
        #pragma unroll
        for (int p = 0; p < PPC; ++p) {
            float2 f = unpk(acc2[p]);
            logit_sm[p * 256 + tid] = f.x + f.y + bv;
        }
        __syncthreads();

        #pragma unroll
        for (int pp = 0; pp < 2; ++pp) {
            int p = wid * 2 + pp;
            const float* L = &logit_sm[p * 256];
            float vv[8];
            #pragma unroll
            for (int i = 0; i < 8; ++i) vv[i] = L[lane + 32 * i];
            float m = vv[0];
            #pragma unroll
            for (int i = 1; i < 8; ++i) m = fmaxf(m, vv[i]);
            for (int off = 16; off; off >>= 1)
                m = fmaxf(m, __shfl_xor_sync(0xffffffffu, m, off));
            float s = 0.0f;
            #pragma unroll
            for (int i = 0; i < 8; ++i) s += expf(vv[i] - m);
            for (int off = 16; off; off >>= 1)
                s += __shfl_xor_sync(0xffffffffu, s, off);
            if (lane == 0) {
                int pos = pos0 + p;
                int b   = pos & 7;
                int t   = pos >> 3;
                int y   = __ldg(&ys[b * T + t]);
                redp[p] = (m + logf(s)) - L[y];
            }
        }
        __syncthreads();
        if (tid == 0) {
            float ssum = 0.0f;
            #pragma unroll
            for (int p = 0; p < PPC; ++p) ssum += redp[p];
            cta_sum += ssum;
        }
        __syncthreads();
    }

    // ---- deterministic final reduction by the last-arriving CTA ----
    if (tid == 0) {
        g_partials[cta] = cta_sum;
        __threadfence();
        unsigned old = atomicAdd(&g_ticket, 1u);
        s_win = ((old % GRID) == (GRID - 1)) ? 1 : 0;
    }
    __syncthreads();
    if (s_win) {
        __threadfence();
        float* r2 = (float*)smem;
        float s = (tid < GRID) ? __ldcg(&g_partials[tid]) : 0.0f;
        r2[tid] = s;
        __syncthreads();
        for (int off = 128; off; off >>= 1) {
            if (tid < off) r2[tid] += r2[tid + off];
            __syncthreads();
        }
        if (tid == 0) out[0] = r2[0] / (float)(B * T);
    }
}

// ---------------- launch ----------------
extern "C" void kernel_launch(void* const* d_in, const int* in_sizes, int n_in,
                              void* d_out, int out_size)
{
    const int*   Xs   = (const int*)d_in[0];
    const int*   ys   = (const int*)d_in[1];
    /* d_in[2] = predict (always 0 here) */
    const float* W_ih = (const float*)d_in[3];
    const float* W_hh = (const float*)d_in[4];
    const float* b_ih = (const float*)d_in[5];
    const float* b_hh = (const float*)d_in[6];
    const float* W1   = (const float*)d_in[7];
    const float* b1   = (const float*)d_in[8];
    float* out = (float*)d_out;

    cudaFuncSetAttribute(charrnn_kernel,
                         cudaFuncAttributeMaxDynamicSharedMemorySize, SMEM_DYN);

    charrnn_kernel<<<GRID, NTHR, SMEM_DYN>>>(Xs, ys, W_ih, W_hh, b_ih, b_hh,
                                             W1, b1, out);
    (void)in_sizes; (void)n_in; (void)out_size;
}

// round 12
// speedup vs baseline: 2.6495x; 1.5942x over previous
#include <cuda_runtime.h>
#include <math.h>

#define B 8
#define T 2048
#define H 1024
#define V 256
#define GRID 128
#define NTHR 256
#define UPC 8            // hidden units per CTA

typedef unsigned long long ull;

#define PPC 16           // positions per loss chunk
#define CHUNKS 8         // 128 positions per CTA
#define FLAG_STRIDE 8    // 32-byte padded flags

// lstm-phase SMEM:
//   h_s  [8 warps][8 b][132] f32  = 33792 B  (per-warp private K-slice)
//   part [2 parity][8 w][292] f32 = 18688 B  (32 rows x 9 + pad)
//   bias [32] f32
#define PH_HS    0
#define PH_PART  33792
#define PH_BIAS  52480
// loss-phase SMEM: h[PPC][1024] | logits[PPC][256] | red[PPC]
#define SMEM_DYN (PPC*1024*4 + PPC*256*4 + 64)

// ---------------- device scratch (static; no allocation) ----------------
__device__ float    g_hs[B * T * H];             // hidden states, [t][b][j]
__device__ float    g_hbuf[2][B][H];             // double-buffered h
__device__ unsigned g_flags[GRID * FLAG_STRIDE]; // monotonic per-CTA counters
__device__ float    g_partials[GRID];
__device__ unsigned g_ticket;

// ---------------- helpers ----------------
__device__ __forceinline__ ull fma2(ull a, ull b, ull c) {
    ull d;
    asm("fma.rn.f32x2 %0, %1, %2, %3;" : "=l"(d) : "l"(a), "l"(b), "l"(c));
    return d;
}
__device__ __forceinline__ float2 unpk(ull v) {
    float2 r;
    asm("mov.b64 {%0, %1}, %2;" : "=f"(r.x), "=f"(r.y) : "l"(v));
    return r;
}
__device__ __forceinline__ unsigned ld_cgv(const unsigned* p) {
    unsigned v;
    asm volatile("ld.global.cg.u32 %0, [%1];" : "=r"(v) : "l"(p));
    return v;
}
__device__ __forceinline__ unsigned ld_acq(const unsigned* p) {
    unsigned v;
    asm volatile("ld.acquire.gpu.global.u32 %0, [%1];" : "=r"(v) : "l"(p));
    return v;
}
__device__ __forceinline__ void st_rel(unsigned* p, unsigned v) {
    asm volatile("st.release.gpu.global.u32 [%0], %1;" :: "l"(p), "r"(v) : "memory");
}
__device__ __forceinline__ void fence_acq() {
    asm volatile("fence.acq_rel.gpu;" ::: "memory");
}
__device__ __forceinline__ float tanh_fast(float x) {
    return 2.0f / (1.0f + __expf(-2.0f * x)) - 1.0f;
}
__device__ __forceinline__ float sigmoid_fast(float x) {
    return 1.0f / (1.0f + __expf(-x));
}
__device__ __forceinline__ unsigned f2tf32(float f) {
    unsigned r;
    asm("cvt.rna.tf32.f32 %0, %1;" : "=r"(r) : "f"(f));
    return r;
}
// m16n8k8 tf32 MMA, fp32 accumulate (warp-wide, sm_80+)
__device__ __forceinline__ void mma_tf32(float* d, const unsigned* a,
                                         unsigned b0, unsigned b1) {
    asm volatile(
        "mma.sync.aligned.m16n8k8.row.col.f32.tf32.tf32.f32 "
        "{%0,%1,%2,%3}, {%4,%5,%6,%7}, {%8,%9}, {%0,%1,%2,%3};"
        : "+f"(d[0]), "+f"(d[1]), "+f"(d[2]), "+f"(d[3])
        : "r"(a[0]), "r"(a[1]), "r"(a[2]), "r"(a[3]), "r"(b0), "r"(b1));
}

// ---------------- single fused persistent kernel ----------------
__global__ void __launch_bounds__(NTHR, 1)
charrnn_kernel(const int* __restrict__ Xs,
               const int* __restrict__ ys,
               const float* __restrict__ W_ih,
               const float* __restrict__ W_hh,
               const float* __restrict__ b_ih,
               const float* __restrict__ b_hh,
               const float* __restrict__ W1,
               const float* __restrict__ b1,
               float* __restrict__ out)
{
    extern __shared__ char smem[];
    float* h_s    = (float*)(smem + PH_HS);      // [8][8][132]
    float* part   = (float*)(smem + PH_PART);    // [2][8][292]
    float* bias_s = (float*)(smem + PH_BIAS);    // [32] (g*8+u)
    __shared__ int s_win;

    const int tid  = threadIdx.x;
    const int wid  = tid >> 5;
    const int lane = tid & 31;
    const int cta  = blockIdx.x;
    const int j0   = cta * UPC;

    // monotonic flag base
    unsigned* myflag = &g_flags[cta * FLAG_STRIDE];
    const unsigned fbase = ld_cgv(myflag);
    // per-lane poll target: producer of the f4 column this lane stages
    const unsigned* pollflag = &g_flags[(16 * wid + (lane >> 1)) * FLAG_STRIDE];
    // warp-0 end-phase poll targets (4 flags per lane)
    const unsigned* fl0 = &g_flags[(lane)      * FLAG_STRIDE];
    const unsigned* fl1 = &g_flags[(lane + 32) * FLAG_STRIDE];
    const unsigned* fl2 = &g_flags[(lane + 64) * FLAG_STRIDE];
    const unsigned* fl3 = &g_flags[(lane + 96) * FLAG_STRIDE];

    // ---- A fragments (once): warp wid owns K-slice [wid*128, wid*128+128)
    unsigned wA[2][16][4];   // 128 regs
    {
        const int ks = wid * 128;
        const int rlo = lane >> 2;
        const int kc  = lane & 3;
        #pragma unroll
        for (int m = 0; m < 2; ++m) {
            #pragma unroll
            for (int k8 = 0; k8 < 16; ++k8) {
                int r0 = m * 16 + rlo;
                int r1 = r0 + 8;
                int kk = ks + k8 * 8 + kc;
                int g0 = r0 >> 3, u0g = r0 & 7;
                int g1 = r1 >> 3, u1g = r1 & 7;
                const float* row0 = &W_hh[(g0 * H + j0 + u0g) * H];
                const float* row1 = &W_hh[(g1 * H + j0 + u1g) * H];
                wA[m][k8][0] = f2tf32(row0[kk]);
                wA[m][k8][1] = f2tf32(row1[kk]);
                wA[m][k8][2] = f2tf32(row0[kk + 4]);
                wA[m][k8][3] = f2tf32(row1[kk + 4]);
            }
        }
    }
    if (tid < 32) {
        int g = tid >> 3, u = tid & 7;
        bias_s[tid] = b_ih[g * H + j0 + u] + b_hh[g * H + j0 + u];
    }
    // zero private h slices (t=0 uses h=0)
    for (int i = tid; i < 8 * 8 * 132; i += NTHR) h_s[i] = 0.0f;
    __syncthreads();

    // epilogue constants: thread tid<64 owns cell (u = tid&7, b = tid>>3)
    const int eu = tid & 7, eb = tid >> 3;
    const int ej = j0 + eu;
    float c_reg = 0.0f;

    float* h_sw = &h_s[wid * 1056];              // this warp's [8][132] slice
    const float* hB = &h_sw[(lane >> 2) * 132 + (lane & 3)];
    float* pw0 = &part[wid * 292];               // parity 0
    float* pw1 = &part[2336 + wid * 292];        // parity 1
    const int prow = lane >> 2, pcol = 2 * (lane & 3);

    // ================= recurrence =================
    for (int t = 0; t < T; ++t) {
        // prefetch input contribution (independent of h_t)
        float wi0 = 0.f, wi1 = 0.f, wi2 = 0.f, wi3 = 0.f;
        if (tid < 64) {
            int x = __ldg(&Xs[eb * T + t]);
            wi0 = __ldg(&W_ih[(0*H + ej) * V + x]);
            wi1 = __ldg(&W_ih[(1*H + ej) * V + x]);
            wi2 = __ldg(&W_ih[(2*H + ej) * V + x]);
            wi3 = __ldg(&W_ih[(3*H + ej) * V + x]);
        }

        if (t > 0) {
            // per-lane wait: poll ONLY the producer this lane stages from
            const unsigned tgt = fbase + (unsigned)t;
            while (ld_cgv(pollflag) < tgt) { }
            (void)ld_acq(pollflag);              // ordering for staged reads
            // stage this lane's f4 column (32*wid + lane) for all 8 b rows
            const float4* hb = (const float4*)g_hbuf[t & 1];
            #pragma unroll
            for (int b2 = 0; b2 < B; ++b2) {
                float4 v = __ldcg(hb + b2 * 256 + 32 * wid + lane);
                *(float4*)&h_sw[b2 * 132 + 4 * lane] = v;
            }
            __syncwarp();
        }

        // ---- tensor-core gate matmul on own K-slice: 32 HMMA per warp ----
        float d0[4] = {0.f, 0.f, 0.f, 0.f};
        float d1[4] = {0.f, 0.f, 0.f, 0.f};
        #pragma unroll
        for (int k8 = 0; k8 < 16; ++k8) {
            float bf0 = hB[k8 * 8];
            float bf1 = hB[k8 * 8 + 4];
            unsigned b0 = f2tf32(bf0), b1 = f2tf32(bf1);
            mma_tf32(d0, wA[0][k8], b0, b1);
            mma_tf32(d1, wA[1][k8], b0, b1);
        }
        __syncwarp();                            // WAR: h_sw reuse next step

        // store per-warp partials (parity-double-buffered)
        float* pw = (t & 1) ? pw1 : pw0;
        pw[(prow     ) * 9 + pcol    ] = d0[0];
        pw[(prow     ) * 9 + pcol + 1] = d0[1];
        pw[(prow +  8) * 9 + pcol    ] = d0[2];
        pw[(prow +  8) * 9 + pcol + 1] = d0[3];
        pw[(prow + 16) * 9 + pcol    ] = d1[0];
        pw[(prow + 16) * 9 + pcol + 1] = d1[1];
        pw[(prow + 24) * 9 + pcol    ] = d1[2];
        pw[(prow + 24) * 9 + pcol + 1] = d1[3];
        __syncthreads();       // the ONLY CTA-wide barrier per step

        // ---- epilogue: warps 0,1 only; others run ahead to t+1 ----
        if (tid < 64) {
            const float* pbase = &part[(t & 1) ? 2336 : 0];
            float S0 = 0.f, S1 = 0.f, S2 = 0.f, S3 = 0.f;
            #pragma unroll
            for (int w = 0; w < 8; ++w) {
                const float* pp = pbase + w * 292;
                S0 += pp[(0*8 + eu) * 9 + eb];
                S1 += pp[(1*8 + eu) * 9 + eb];
                S2 += pp[(2*8 + eu) * 9 + eb];
                S3 += pp[(3*8 + eu) * 9 + eb];
            }
            S0 += wi0 + bias_s[0*8 + eu];
            S1 += wi1 + bias_s[1*8 + eu];
            S2 += wi2 + bias_s[2*8 + eu];
            S3 += wi3 + bias_s[3*8 + eu];
            float ig = sigmoid_fast(S0);
            float fg = sigmoid_fast(S1);
            float gg = tanh_fast(S2);
            float og = sigmoid_fast(S3);
            c_reg = fg * c_reg + ig * gg;
            float hnew = og * tanh_fast(c_reg);
            g_hbuf[(t + 1) & 1][eb][ej] = hnew;
            asm volatile("bar.sync 1, 64;" ::: "memory");
            if (tid == 0) st_rel(myflag, fbase + (unsigned)(t + 1));
            // off-critical-path archive
            g_hs[(t * B + eb) * H + ej] = hnew;
        }
    }

    // ---- publish archives; wait for all CTAs ----
    __threadfence();
    __syncthreads();
    if (tid == 0) st_rel(myflag, fbase + (unsigned)(T + 1));
    if (wid == 0) {
        const unsigned tgt = fbase + (unsigned)(T + 1);
        bool d0 = false, d1 = false, d2 = false, d3 = false;
        while (true) {
            if (!d0) d0 = ld_cgv(fl0) >= tgt;
            if (!d1) d1 = ld_cgv(fl1) >= tgt;
            if (!d2) d2 = ld_cgv(fl2) >= tgt;
            if (!d3) d3 = ld_cgv(fl3) >= tgt;
            if (__all_sync(0xffffffffu, d0 && d1 && d2 && d3)) break;
            __nanosleep(64);
        }
        fence_acq();
    }
    __syncthreads();

    // ================= loss phase: 128 positions per CTA =================
    float* h_sm     = (float*)smem;                              // [PPC][1024]
    float* logit_sm = (float*)(smem + PPC*1024*4);               // [PPC][256]
    float* redp     = (float*)(smem + PPC*1024*4 + PPC*256*4);   // [PPC]

    float cta_sum = 0.0f;

    for (int chunk = 0; chunk < CHUNKS; ++chunk) {
        const int pos0 = cta * 128 + chunk * PPC;                // pos = t*B + b

        for (int idx4 = tid; idx4 < PPC * 1024 / 4; idx4 += NTHR) {
            *(float4*)&h_sm[idx4 * 4] =
                __ldcg((const float4*)&g_hs[pos0 * 1024] + idx4);
        }
        __syncthreads();

        ull acc2[PPC];
        #pragma unroll
        for (int p = 0; p < PPC; ++p) acc2[p] = 0ull;

        const ulonglong2* wrow = (const ulonglong2*)&W1[tid * 1024];
        for (int k4 = 0; k4 < 256; ++k4) {
            ulonglong2 w = __ldg(wrow + k4);
            #pragma unroll
            for (int p = 0; p < PPC; ++p) {
                ulonglong2 hv = *(const ulonglong2*)&h_sm[p * 1024 + k4 * 4];
                acc2[p] = fma2(w.x, hv.x, acc2[p]);
                acc2[p] = fma2(w.y, hv.y, acc2[p]);
            }
        }
        float bv = b1[tid];
        #pragma unroll
        for (int p = 0; p < PPC; ++p) {
            float2 f = unpk(acc2[p]);
            logit_sm[p * 256 + tid] = f.x + f.y + bv;
        }
        __syncthreads();

        #pragma unroll
        for (int pp = 0; pp < 2; ++pp) {
            int p = wid * 2 + pp;
            const float* L = &logit_sm[p * 256];
            float vv[8];
            #pragma unroll
            for (int i = 0; i < 8; ++i) vv[i] = L[lane + 32 * i];
            float m = vv[0];
            #pragma unroll
            for (int i = 1; i < 8; ++i) m = fmaxf(m, vv[i]);
            for (int off = 16; off; off >>= 1)
                m = fmaxf(m, __shfl_xor_sync(0xffffffffu, m, off));
            float s = 0.0f;
            #pragma unroll
            for (int i = 0; i < 8; ++i) s += expf(vv[i] - m);
            for (int off = 16; off; off >>= 1)
                s += __shfl_xor_sync(0xffffffffu, s, off);
            if (lane == 0) {
                int pos = pos0 + p;
                int b   = pos & 7;
                int t   = pos >> 3;
                int y   = __ldg(&ys[b * T + t]);
                redp[p] = (m + logf(s)) - L[y];
            }
        }
        __syncthreads();
        if (tid == 0) {
            float ssum = 0.0f;
            #pragma unroll
            for (int p = 0; p < PPC; ++p) ssum += redp[p];
            cta_sum += ssum;
        }
        __syncthreads();
    }

    // ---- deterministic final reduction by the last-arriving CTA ----
    if (tid == 0) {
        g_partials[cta] = cta_sum;
        __threadfence();
        unsigned old = atomicAdd(&g_ticket, 1u);
        s_win = ((old % GRID) == (GRID - 1)) ? 1 : 0;
    }
    __syncthreads();
    if (s_win) {
        __threadfence();
        float* r2 = (float*)smem;
        float s = (tid < GRID) ? __ldcg(&g_partials[tid]) : 0.0f;
        r2[tid] = s;
        __syncthreads();
        for (int off = 128; off; off >>= 1) {
            if (tid < off) r2[tid] += r2[tid + off];
            __syncthreads();
        }
        if (tid == 0) out[0] = r2[0] / (float)(B * T);
    }
}

// ---------------- launch ----------------
extern "C" void kernel_launch(void* const* d_in, const int* in_sizes, int n_in,
                              void* d_out, int out_size)
{
    const int*   Xs   = (const int*)d_in[0];
    const int*   ys   = (const int*)d_in[1];
    /* d_in[2] = predict (always 0 here) */
    const float* W_ih = (const float*)d_in[3];
    const float* W_hh = (const float*)d_in[4];
    const float* b_ih = (const float*)d_in[5];
    const float* b_hh = (const float*)d_in[6];
    const float* W1   = (const float*)d_in[7];
    const float* b1   = (const float*)d_in[8];
    float* out = (float*)d_out;

    cudaFuncSetAttribute(charrnn_kernel,
                         cudaFuncAttributeMaxDynamicSharedMemorySize, SMEM_DYN);

    charrnn_kernel<<<GRID, NTHR, SMEM_DYN>>>(Xs, ys, W_ih, W_hh, b_ih, b_hh,
                                             W1, b1, out);
    (void)in_sizes; (void)n_in; (void)out_size;
}

// round 13
// speedup vs baseline: 3.1794x; 1.2000x over previous
#include <cuda_runtime.h>
#include <math.h>

#define B 8
#define T 2048
#define H 1024
#define V 256
#define GRID 128
#define NTHR 320         // 8 MMA warps + 2 epilogue warps
#define UPC 8            // hidden units per CTA

typedef unsigned long long ull;

#define PPC 16           // positions per loss chunk
#define CHUNKS 8         // 128 positions per CTA
#define FLAG_STRIDE 8    // 32-byte padded flags

// lstm-phase SMEM:
//   h_s  [8 warps][8 b][132] f32  = 33792 B  (per-warp private K-slice)
//   part [2 parity][8 w][292] f32 = 18688 B
//   bias [32] f32
#define PH_HS    0
#define PH_PART  33792
#define PH_BIAS  52480
// loss-phase SMEM: h[PPC][1024] | logits[PPC][256] | red[PPC]
#define SMEM_DYN (PPC*1024*4 + PPC*256*4 + 64)

// ---------------- device scratch (static; no allocation) ----------------
__device__ float    g_hs[B * T * H];             // hidden states, [t][b][j]
__device__ float    g_hbuf[2][B][H];             // double-buffered h
__device__ unsigned g_flags[GRID * FLAG_STRIDE]; // monotonic per-CTA counters
__device__ float    g_partials[GRID];
__device__ unsigned g_ticket;

// ---------------- helpers ----------------
__device__ __forceinline__ ull fma2(ull a, ull b, ull c) {
    ull d;
    asm("fma.rn.f32x2 %0, %1, %2, %3;" : "=l"(d) : "l"(a), "l"(b), "l"(c));
    return d;
}
__device__ __forceinline__ float2 unpk(ull v) {
    float2 r;
    asm("mov.b64 {%0, %1}, %2;" : "=f"(r.x), "=f"(r.y) : "l"(v));
    return r;
}
__device__ __forceinline__ unsigned ld_cgv(const unsigned* p) {
    unsigned v;
    asm volatile("ld.global.cg.u32 %0, [%1];" : "=r"(v) : "l"(p));
    return v;
}
__device__ __forceinline__ unsigned ld_acq(const unsigned* p) {
    unsigned v;
    asm volatile("ld.acquire.gpu.global.u32 %0, [%1];" : "=r"(v) : "l"(p));
    return v;
}
__device__ __forceinline__ void st_rel(unsigned* p, unsigned v) {
    asm volatile("st.release.gpu.global.u32 [%0], %1;" :: "l"(p), "r"(v) : "memory");
}
__device__ __forceinline__ void fence_acq() {
    asm volatile("fence.acq_rel.gpu;" ::: "memory");
}
__device__ __forceinline__ float tanh_fast(float x) {
    return 2.0f / (1.0f + __expf(-2.0f * x)) - 1.0f;
}
__device__ __forceinline__ float sigmoid_fast(float x) {
    return 1.0f / (1.0f + __expf(-x));
}
__device__ __forceinline__ unsigned f2tf32(float f) {
    unsigned r;
    asm("cvt.rna.tf32.f32 %0, %1;" : "=r"(r) : "f"(f));
    return r;
}
// m16n8k8 tf32 MMA, fp32 accumulate
__device__ __forceinline__ void mma_tf32(float* d, const unsigned* a,
                                         unsigned b0, unsigned b1) {
    asm volatile(
        "mma.sync.aligned.m16n8k8.row.col.f32.tf32.tf32.f32 "
        "{%0,%1,%2,%3}, {%4,%5,%6,%7}, {%8,%9}, {%0,%1,%2,%3};"
        : "+f"(d[0]), "+f"(d[1]), "+f"(d[2]), "+f"(d[3])
        : "r"(a[0]), "r"(a[1]), "r"(a[2]), "r"(a[3]), "r"(b0), "r"(b1));
}

// ---------------- single fused persistent kernel ----------------
__global__ void __launch_bounds__(NTHR, 1)
charrnn_kernel(const int* __restrict__ Xs,
               const int* __restrict__ ys,
               const float* __restrict__ W_ih,
               const float* __restrict__ W_hh,
               const float* __restrict__ b_ih,
               const float* __restrict__ b_hh,
               const float* __restrict__ W1,
               const float* __restrict__ b1,
               float* __restrict__ out)
{
    extern __shared__ char smem[];
    float* h_s    = (float*)(smem + PH_HS);      // [8][8][132]
    float* part   = (float*)(smem + PH_PART);    // [2][8][292]
    float* bias_s = (float*)(smem + PH_BIAS);    // [32] (g*8+u)
    __shared__ int s_win;

    const int tid  = threadIdx.x;
    const int wid  = tid >> 5;
    const int lane = tid & 31;
    const int cta  = blockIdx.x;
    const int j0   = cta * UPC;
    const int mwid = wid & 7;                    // clamp for safe addressing

    // monotonic flag base
    unsigned* myflag = &g_flags[cta * FLAG_STRIDE];
    const unsigned fbase = ld_cgv(myflag);
    // per-lane poll target for MMA warps
    const unsigned* pollflag = &g_flags[(16 * mwid + (lane >> 1)) * FLAG_STRIDE];
    // warp-0 end-phase poll targets
    const unsigned* fl0 = &g_flags[(lane)      * FLAG_STRIDE];
    const unsigned* fl1 = &g_flags[(lane + 32) * FLAG_STRIDE];
    const unsigned* fl2 = &g_flags[(lane + 64) * FLAG_STRIDE];
    const unsigned* fl3 = &g_flags[(lane + 96) * FLAG_STRIDE];

    // ---- A fragments (MMA warps only): warp mwid owns K-slice [mwid*128, +128)
    unsigned wA[2][16][4];
    if (wid < 8) {
        const int ks = mwid * 128;
        const int rlo = lane >> 2;
        const int kc  = lane & 3;
        #pragma unroll
        for (int m = 0; m < 2; ++m) {
            #pragma unroll
            for (int k8 = 0; k8 < 16; ++k8) {
                int r0 = m * 16 + rlo;
                int r1 = r0 + 8;
                int kk = ks + k8 * 8 + kc;
                int g0 = r0 >> 3, u0g = r0 & 7;
                int g1 = r1 >> 3, u1g = r1 & 7;
                const float* row0 = &W_hh[(g0 * H + j0 + u0g) * H];
                const float* row1 = &W_hh[(g1 * H + j0 + u1g) * H];
                wA[m][k8][0] = f2tf32(row0[kk]);
                wA[m][k8][1] = f2tf32(row1[kk]);
                wA[m][k8][2] = f2tf32(row0[kk + 4]);
                wA[m][k8][3] = f2tf32(row1[kk + 4]);
            }
        }
    }
    if (tid < 32) {
        int g = tid >> 3, u = tid & 7;
        bias_s[tid] = b_ih[g * H + j0 + u] + b_hh[g * H + j0 + u];
    }
    // zero private h slices (t=0 uses h=0)
    for (int i = tid; i < 8 * 8 * 132; i += NTHR) h_s[i] = 0.0f;
    __syncthreads();

    float* h_sw = &h_s[mwid * 1056];
    const float* hB = &h_sw[(lane >> 2) * 132 + (lane & 3)];
    float* pw0 = &part[mwid * 292];
    float* pw1 = &part[2336 + mwid * 292];
    const int prow = lane >> 2, pcol = 2 * (lane & 3);

    // epilogue constants (warps 8,9): etid 0..63 -> cell (u = etid&7, b = etid>>3)
    const int etid = tid - 256;
    const int eu = etid & 7, eb = etid >> 3;
    const int ej = j0 + eu;
    float c_reg = 0.0f;

    // ================= recurrence (warp-specialized) =================
    if (wid < 8) {
        // ---------- MMA warps ----------
        for (int t = 0; t < T; ++t) {
            if (t > 0) {
                const unsigned tgt = fbase + (unsigned)t;
                while (ld_cgv(pollflag) < tgt) { }
                (void)ld_acq(pollflag);
                const float4* hb = (const float4*)g_hbuf[t & 1];
                #pragma unroll
                for (int b2 = 0; b2 < B; ++b2) {
                    float4 v = __ldcg(hb + b2 * 256 + 32 * mwid + lane);
                    *(float4*)&h_sw[b2 * 132 + 4 * lane] = v;
                }
                __syncwarp();
            }

            float d0[4] = {0.f, 0.f, 0.f, 0.f};
            float d1[4] = {0.f, 0.f, 0.f, 0.f};
            #pragma unroll
            for (int k8 = 0; k8 < 16; ++k8) {
                float bf0 = hB[k8 * 8];
                float bf1 = hB[k8 * 8 + 4];
                unsigned b0 = f2tf32(bf0), b1 = f2tf32(bf1);
                mma_tf32(d0, wA[0][k8], b0, b1);
                mma_tf32(d1, wA[1][k8], b0, b1);
            }
            __syncwarp();                        // WAR: h_sw reuse next step

            float* pw = (t & 1) ? pw1 : pw0;
            pw[(prow     ) * 9 + pcol    ] = d0[0];
            pw[(prow     ) * 9 + pcol + 1] = d0[1];
            pw[(prow +  8) * 9 + pcol    ] = d0[2];
            pw[(prow +  8) * 9 + pcol + 1] = d0[3];
            pw[(prow + 16) * 9 + pcol    ] = d1[0];
            pw[(prow + 16) * 9 + pcol + 1] = d1[1];
            pw[(prow + 24) * 9 + pcol    ] = d1[2];
            pw[(prow + 24) * 9 + pcol + 1] = d1[3];
            asm volatile("bar.sync 1, %0;" :: "n"(NTHR) : "memory");
            // immediately proceed to t+1 (epilogue overlaps)
        }
    } else {
        // ---------- epilogue warps ----------
        for (int t = 0; t < T; ++t) {
            // prefetch input contribution (independent of h_t) during MMA
            int x = __ldg(&Xs[eb * T + t]);
            float wi0 = __ldg(&W_ih[(0*H + ej) * V + x]);
            float wi1 = __ldg(&W_ih[(1*H + ej) * V + x]);
            float wi2 = __ldg(&W_ih[(2*H + ej) * V + x]);
            float wi3 = __ldg(&W_ih[(3*H + ej) * V + x]);

            asm volatile("bar.sync 1, %0;" :: "n"(NTHR) : "memory");

            const float* pbase = &part[(t & 1) ? 2336 : 0];
            float S0 = 0.f, S1 = 0.f, S2 = 0.f, S3 = 0.f;
            #pragma unroll
            for (int w = 0; w < 8; ++w) {
                const float* pp = pbase + w * 292;
                S0 += pp[(0*8 + eu) * 9 + eb];
                S1 += pp[(1*8 + eu) * 9 + eb];
                S2 += pp[(2*8 + eu) * 9 + eb];
                S3 += pp[(3*8 + eu) * 9 + eb];
            }
            S0 += wi0 + bias_s[0*8 + eu];
            S1 += wi1 + bias_s[1*8 + eu];
            S2 += wi2 + bias_s[2*8 + eu];
            S3 += wi3 + bias_s[3*8 + eu];
            float ig = sigmoid_fast(S0);
            float fg = sigmoid_fast(S1);
            float gg = tanh_fast(S2);
            float og = sigmoid_fast(S3);
            c_reg = fg * c_reg + ig * gg;
            float hnew = og * tanh_fast(c_reg);
            g_hbuf[(t + 1) & 1][eb][ej] = hnew;
            asm volatile("bar.sync 2, 64;" ::: "memory");
            if (etid == 0) st_rel(myflag, fbase + (unsigned)(t + 1));
            // off-critical-path archive
            g_hs[(t * B + eb) * H + ej] = hnew;
        }
    }

    // ---- publish archives; wait for all CTAs ----
    __threadfence();
    __syncthreads();
    if (tid == 0) st_rel(myflag, fbase + (unsigned)(T + 1));
    if (wid == 0) {
        const unsigned tgt = fbase + (unsigned)(T + 1);
        bool d0 = false, d1 = false, d2 = false, d3 = false;
        while (true) {
            if (!d0) d0 = ld_cgv(fl0) >= tgt;
            if (!d1) d1 = ld_cgv(fl1) >= tgt;
            if (!d2) d2 = ld_cgv(fl2) >= tgt;
            if (!d3) d3 = ld_cgv(fl3) >= tgt;
            if (__all_sync(0xffffffffu, d0 && d1 && d2 && d3)) break;
            __nanosleep(64);
        }
        fence_acq();
    }
    __syncthreads();

    // ================= loss phase: 128 positions per CTA =================
    float* h_sm     = (float*)smem;                              // [PPC][1024]
    float* logit_sm = (float*)(smem + PPC*1024*4);               // [PPC][256]
    float* redp     = (float*)(smem + PPC*1024*4 + PPC*256*4);   // [PPC]

    float cta_sum = 0.0f;

    for (int chunk = 0; chunk < CHUNKS; ++chunk) {
        const int pos0 = cta * 128 + chunk * PPC;                // pos = t*B + b

        for (int idx4 = tid; idx4 < PPC * 1024 / 4; idx4 += NTHR) {
            *(float4*)&h_sm[idx4 * 4] =
                __ldcg((const float4*)&g_hs[pos0 * 1024] + idx4);
        }
        __syncthreads();

        if (tid < 256) {
            ull acc2[PPC];
            #pragma unroll
            for (int p = 0; p < PPC; ++p) acc2[p] = 0ull;

            const ulonglong2* wrow = (const ulonglong2*)&W1[tid * 1024];
            for (int k4 = 0; k4 < 256; ++k4) {
                ulonglong2 w = __ldg(wrow + k4);
                #pragma unroll
                for (int p = 0; p < PPC; ++p) {
                    ulonglong2 hv = *(const ulonglong2*)&h_sm[p * 1024 + k4 * 4];
                    acc2[p] = fma2(w.x, hv.x, acc2[p]);
                    acc2[p] = fma2(w.y, hv.y, acc2[p]);
                }
            }
            float bv = b1[tid];
            #pragma unroll
            for (int p = 0; p < PPC; ++p) {
                float2 f = unpk(acc2[p]);
                logit_sm[p * 256 + tid] = f.x + f.y + bv;
            }
        }
        __syncthreads();

        if (wid < 8) {
            #pragma unroll
            for (int pp = 0; pp < 2; ++pp) {
                int p = wid * 2 + pp;
                const float* L = &logit_sm[p * 256];
                float vv[8];
                #pragma unroll
                for (int i = 0; i < 8; ++i) vv[i] = L[lane + 32 * i];
                float m = vv[0];
                #pragma unroll
                for (int i = 1; i < 8; ++i) m = fmaxf(m, vv[i]);
                for (int off = 16; off; off >>= 1)
                    m = fmaxf(m, __shfl_xor_sync(0xffffffffu, m, off));
                float s = 0.0f;
                #pragma unroll
                for (int i = 0; i < 8; ++i) s += expf(vv[i] - m);
                for (int off = 16; off; off >>= 1)
                    s += __shfl_xor_sync(0xffffffffu, s, off);
                if (lane == 0) {
                    int pos = pos0 + p;
                    int b   = pos & 7;
                    int t   = pos >> 3;
                    int y   = __ldg(&ys[b * T + t]);
                    redp[p] = (m + logf(s)) - L[y];
                }
            }
        }
        __syncthreads();
        if (tid == 0) {
            float ssum = 0.0f;
            #pragma unroll
            for (int p = 0; p < PPC; ++p) ssum += redp[p];
            cta_sum += ssum;
        }
        __syncthreads();
    }

    // ---- deterministic final reduction by the last-arriving CTA ----
    if (tid == 0) {
        g_partials[cta] = cta_sum;
        __threadfence();
        unsigned old = atomicAdd(&g_ticket, 1u);
        s_win = ((old % GRID) == (GRID - 1)) ? 1 : 0;
    }
    __syncthreads();
    if (s_win) {
        __threadfence();
        float* r2 = (float*)smem;
        if (tid < GRID) r2[tid] = __ldcg(&g_partials[tid]);
        __syncthreads();
        for (int off = 64; off; off >>= 1) {
            if (tid < off) r2[tid] += r2[tid + off];
            __syncthreads();
        }
        if (tid == 0) out[0] = r2[0] / (float)(B * T);
    }
}

// ---------------- launch ----------------
extern "C" void kernel_launch(void* const* d_in, const int* in_sizes, int n_in,
                              void* d_out, int out_size)
{
    const int*   Xs   = (const int*)d_in[0];
    const int*   ys   = (const int*)d_in[1];
    /* d_in[2] = predict (always 0 here) */
    const float* W_ih = (const float*)d_in[3];
    const float* W_hh = (const float*)d_in[4];
    const float* b_ih = (const float*)d_in[5];
    const float* b_hh = (const float*)d_in[6];
    const float* W1   = (const float*)d_in[7];
    const float* b1   = (const float*)d_in[8];
    float* out = (float*)d_out;

    cudaFuncSetAttribute(charrnn_kernel,
                         cudaFuncAttributeMaxDynamicSharedMemorySize, SMEM_DYN);

    charrnn_kernel<<<GRID, NTHR, SMEM_DYN>>>(Xs, ys, W_ih, W_hh, b_ih, b_hh,
                                             W1, b1, out);
    (void)in_sizes; (void)n_in; (void)out_size;
}

// round 15
// speedup vs baseline: 3.1988x; 1.0061x over previous
#include <cuda_runtime.h>
#include <math.h>

#define B 8
#define T 2048
#define H 1024
#define V 256
#define GRID 128
#define NTHR 384         // 8 MMA warps + 4 epilogue warps
#define UPC 8            // hidden units per CTA

typedef unsigned long long ull;

#define PPC 16           // positions per loss chunk
#define CHUNKS 8         // 128 positions per CTA
#define FLAG_STRIDE 8    // 32-byte padded flags

// lstm-phase SMEM:
//   h_s  [8 warps][8 b][132] f32  = 33792 B  (per-warp private K-slice)
//   part [2 parity][8 w][292] f32 = 18688 B
//   bias [32] f32
#define PH_HS    0
#define PH_PART  33792
#define PH_BIAS  52480
// loss-phase SMEM: h[PPC][1024] | logits[PPC][256] | red[PPC]
#define SMEM_DYN (PPC*1024*4 + PPC*256*4 + 64)

// ---------------- device scratch (static; no allocation) ----------------
__device__ float    g_hs[B * T * H];             // hidden states, [t][b][j]
__device__ float    g_hbuf[2][B][H];             // double-buffered h
__device__ unsigned g_flags[GRID * FLAG_STRIDE]; // monotonic per-CTA counters
__device__ float    g_partials[GRID];
__device__ unsigned g_ticket;

// ---------------- helpers ----------------
__device__ __forceinline__ ull fma2(ull a, ull b, ull c) {
    ull d;
    asm("fma.rn.f32x2 %0, %1, %2, %3;" : "=l"(d) : "l"(a), "l"(b), "l"(c));
    return d;
}
__device__ __forceinline__ float2 unpk(ull v) {
    float2 r;
    asm("mov.b64 {%0, %1}, %2;" : "=f"(r.x), "=f"(r.y) : "l"(v));
    return r;
}
__device__ __forceinline__ unsigned ld_cgv(const unsigned* p) {
    unsigned v;
    asm volatile("ld.global.cg.u32 %0, [%1];" : "=r"(v) : "l"(p));
    return v;
}
__device__ __forceinline__ unsigned ld_acq(const unsigned* p) {
    unsigned v;
    asm volatile("ld.acquire.gpu.global.u32 %0, [%1];" : "=r"(v) : "l"(p));
    return v;
}
__device__ __forceinline__ void st_rel(unsigned* p, unsigned v) {
    asm volatile("st.release.gpu.global.u32 [%0], %1;" :: "l"(p), "r"(v) : "memory");
}
__device__ __forceinline__ void fence_acq() {
    asm volatile("fence.acq_rel.gpu;" ::: "memory");
}
__device__ __forceinline__ float tanh_fast(float x) {
    return 2.0f / (1.0f + __expf(-2.0f * x)) - 1.0f;
}
__device__ __forceinline__ float sigmoid_fast(float x) {
    return 1.0f / (1.0f + __expf(-x));
}
__device__ __forceinline__ unsigned f2tf32(float f) {
    unsigned r;
    asm("cvt.rna.tf32.f32 %0, %1;" : "=r"(r) : "f"(f));
    return r;
}
// m16n8k8 tf32 MMA, fp32 accumulate
__device__ __forceinline__ void mma_tf32(float* d, const unsigned* a,
                                         unsigned b0, unsigned b1) {
    asm volatile(
        "mma.sync.aligned.m16n8k8.row.col.f32.tf32.tf32.f32 "
        "{%0,%1,%2,%3}, {%4,%5,%6,%7}, {%8,%9}, {%0,%1,%2,%3};"
        : "+f"(d[0]), "+f"(d[1]), "+f"(d[2]), "+f"(d[3])
        : "r"(a[0]), "r"(a[1]), "r"(a[2]), "r"(a[3]), "r"(b0), "r"(b1));
}

// ---------------- single fused persistent kernel ----------------
__global__ void __launch_bounds__(NTHR, 1)
charrnn_kernel(const int* __restrict__ Xs,
               const int* __restrict__ ys,
               const float* __restrict__ W_ih,
               const float* __restrict__ W_hh,
               const float* __restrict__ b_ih,
               const float* __restrict__ b_hh,
               const float* __restrict__ W1,
               const float* __restrict__ b1,
               float* __restrict__ out)
{
    extern __shared__ char smem[];
    float* h_s    = (float*)(smem + PH_HS);      // [8][8][132]
    float* part   = (float*)(smem + PH_PART);    // [2][8][292]
    float* bias_s = (float*)(smem + PH_BIAS);    // [32] (g*8+u)
    __shared__ int s_win;

    const int tid  = threadIdx.x;
    const int wid  = tid >> 5;
    const int lane = tid & 31;
    const int cta  = blockIdx.x;
    const int j0   = cta * UPC;
    const int mwid = wid & 7;                    // clamp for safe addressing

    // monotonic flag base
    unsigned* myflag = &g_flags[cta * FLAG_STRIDE];
    const unsigned fbase = ld_cgv(myflag);
    // per-lane poll target for MMA warps
    const unsigned* pollflag = &g_flags[(16 * mwid + (lane >> 1)) * FLAG_STRIDE];
    // warp-0 end-phase poll targets
    const unsigned* fl0 = &g_flags[(lane)      * FLAG_STRIDE];
    const unsigned* fl1 = &g_flags[(lane + 32) * FLAG_STRIDE];
    const unsigned* fl2 = &g_flags[(lane + 64) * FLAG_STRIDE];
    const unsigned* fl3 = &g_flags[(lane + 96) * FLAG_STRIDE];

    // ---- A fragments (MMA warps only): warp mwid owns K-slice [mwid*128, +128)
    unsigned wA[2][16][4];
    if (wid < 8) {
        const int ks = mwid * 128;
        const int rlo = lane >> 2;
        const int kc  = lane & 3;
        #pragma unroll
        for (int m = 0; m < 2; ++m) {
            #pragma unroll
            for (int k8 = 0; k8 < 16; ++k8) {
                int r0 = m * 16 + rlo;
                int r1 = r0 + 8;
                int kk = ks + k8 * 8 + kc;
                int g0 = r0 >> 3, u0g = r0 & 7;
                int g1 = r1 >> 3, u1g = r1 & 7;
                const float* row0 = &W_hh[(g0 * H + j0 + u0g) * H];
                const float* row1 = &W_hh[(g1 * H + j0 + u1g) * H];
                wA[m][k8][0] = f2tf32(row0[kk]);
                wA[m][k8][1] = f2tf32(row1[kk]);
                wA[m][k8][2] = f2tf32(row0[kk + 4]);
                wA[m][k8][3] = f2tf32(row1[kk + 4]);
            }
        }
    }
    if (tid < 32) {
        int g = tid >> 3, u = tid & 7;
        bias_s[tid] = b_ih[g * H + j0 + u] + b_hh[g * H + j0 + u];
    }
    // zero private h slices (t=0 uses h=0)
    for (int i = tid; i < 8 * 8 * 132; i += NTHR) h_s[i] = 0.0f;
    __syncthreads();

    float* h_sw = &h_s[mwid * 1056];
    const float* hB = &h_sw[(lane >> 2) * 132 + (lane & 3)];
    float* pw0 = &part[mwid * 292];
    float* pw1 = &part[2336 + mwid * 292];
    const int prow = lane >> 2, pcol = 2 * (lane & 3);

    // epilogue constants (warps 8..11): etid 0..127, 2 threads per cell
    const int etid = tid - 256;
    const int ecell = etid >> 1;                 // 0..63
    const int ehalf = etid & 1;                  // 0: w=0..3, 1: w=4..7
    const int eu = ecell & 7, eb = ecell >> 3;
    const int ej = j0 + eu;
    float c_reg = 0.0f;

    // ================= recurrence (warp-specialized, blocking barrier) ======
    if (wid < 8) {
        // ---------- MMA warps ----------
        for (int t = 0; t < T; ++t) {
            if (t > 0) {
                const unsigned tgt = fbase + (unsigned)t;
                while (ld_cgv(pollflag) < tgt) { }
                (void)ld_acq(pollflag);
                const float4* hb = (const float4*)g_hbuf[t & 1];
                #pragma unroll
                for (int b2 = 0; b2 < B; ++b2) {
                    float4 v = __ldcg(hb + b2 * 256 + 32 * mwid + lane);
                    *(float4*)&h_sw[b2 * 132 + 4 * lane] = v;
                }
                __syncwarp();
            }

            float d0[4] = {0.f, 0.f, 0.f, 0.f};
            float d1[4] = {0.f, 0.f, 0.f, 0.f};
            #pragma unroll
            for (int k8 = 0; k8 < 16; ++k8) {
                float bf0 = hB[k8 * 8];
                float bf1 = hB[k8 * 8 + 4];
                unsigned b0 = f2tf32(bf0), b1 = f2tf32(bf1);
                mma_tf32(d0, wA[0][k8], b0, b1);
                mma_tf32(d1, wA[1][k8], b0, b1);
            }
            __syncwarp();                        // WAR: h_sw reuse next step

            float* pw = (t & 1) ? pw1 : pw0;
            pw[(prow     ) * 9 + pcol    ] = d0[0];
            pw[(prow     ) * 9 + pcol + 1] = d0[1];
            pw[(prow +  8) * 9 + pcol    ] = d0[2];
            pw[(prow +  8) * 9 + pcol + 1] = d0[3];
            pw[(prow + 16) * 9 + pcol    ] = d1[0];
            pw[(prow + 16) * 9 + pcol + 1] = d1[1];
            pw[(prow + 24) * 9 + pcol    ] = d1[2];
            pw[(prow + 24) * 9 + pcol + 1] = d1[3];
            asm volatile("bar.sync 1, %0;" :: "n"(NTHR) : "memory");
            // proceed to t+1 (epilogue overlaps)
        }
    } else {
        // ---------- epilogue warps (128 threads, 2 per cell) ----------
        for (int t = 0; t < T; ++t) {
            // prefetch input contribution (half 0 only; latency drains under bar)
            float wi0 = 0.f, wi1 = 0.f, wi2 = 0.f, wi3 = 0.f;
            if (ehalf == 0) {
                int x = __ldg(&Xs[eb * T + t]);
                wi0 = __ldg(&W_ih[(0*H + ej) * V + x]);
                wi1 = __ldg(&W_ih[(1*H + ej) * V + x]);
                wi2 = __ldg(&W_ih[(2*H + ej) * V + x]);
                wi3 = __ldg(&W_ih[(3*H + ej) * V + x]);
            }

            asm volatile("bar.sync 1, %0;" :: "n"(NTHR) : "memory");

            const float* pbase = &part[(t & 1) ? 2336 : 0];
            float S0 = 0.f, S1 = 0.f, S2 = 0.f, S3 = 0.f;
            #pragma unroll
            for (int wql = 0; wql < 4; ++wql) {
                const float* pp = pbase + (ehalf * 4 + wql) * 292;
                S0 += pp[(0*8 + eu) * 9 + eb];
                S1 += pp[(1*8 + eu) * 9 + eb];
                S2 += pp[(2*8 + eu) * 9 + eb];
                S3 += pp[(3*8 + eu) * 9 + eb];
            }
            // combine the two halves (adjacent lanes)
            S0 += __shfl_xor_sync(0xffffffffu, S0, 1);
            S1 += __shfl_xor_sync(0xffffffffu, S1, 1);
            S2 += __shfl_xor_sync(0xffffffffu, S2, 1);
            S3 += __shfl_xor_sync(0xffffffffu, S3, 1);

            if (ehalf == 0) {
                S0 += wi0 + bias_s[0*8 + eu];
                S1 += wi1 + bias_s[1*8 + eu];
                S2 += wi2 + bias_s[2*8 + eu];
                S3 += wi3 + bias_s[3*8 + eu];
                float ig = sigmoid_fast(S0);
                float fg = sigmoid_fast(S1);
                float gg = tanh_fast(S2);
                float og = sigmoid_fast(S3);
                c_reg = fg * c_reg + ig * gg;
                float hnew = og * tanh_fast(c_reg);
                g_hbuf[(t + 1) & 1][eb][ej] = hnew;
                // archive (consumed only after end-phase global barrier)
                g_hs[(t * B + eb) * H + ej] = hnew;
            }
            asm volatile("bar.sync 5, 128;" ::: "memory");
            if (etid == 0) st_rel(myflag, fbase + (unsigned)(t + 1));
        }
    }

    // ---- publish archives; wait for all CTAs ----
    __threadfence();
    __syncthreads();
    if (tid == 0) st_rel(myflag, fbase + (unsigned)(T + 1));
    if (wid == 0) {
        const unsigned tgt = fbase + (unsigned)(T + 1);
        bool d0 = false, d1 = false, d2 = false, d3 = false;
        while (true) {
            if (!d0) d0 = ld_cgv(fl0) >= tgt;
            if (!d1) d1 = ld_cgv(fl1) >= tgt;
            if (!d2) d2 = ld_cgv(fl2) >= tgt;
            if (!d3) d3 = ld_cgv(fl3) >= tgt;
            if (__all_sync(0xffffffffu, d0 && d1 && d2 && d3)) break;
            __nanosleep(64);
        }
        fence_acq();
    }
    __syncthreads();

    // ================= loss phase: 128 positions per CTA =================
    float* h_sm     = (float*)smem;                              // [PPC][1024]
    float* logit_sm = (float*)(smem + PPC*1024*4);               // [PPC][256]
    float* redp     = (float*)(smem + PPC*1024*4 + PPC*256*4);   // [PPC]

    float cta_sum = 0.0f;

    for (int chunk = 0; chunk < CHUNKS; ++chunk) {
        const int pos0 = cta * 128 + chunk * PPC;                // pos = t*B + b

        for (int idx4 = tid; idx4 < PPC * 1024 / 4; idx4 += NTHR) {
            *(float4*)&h_sm[idx4 * 4] =
                __ldcg((const float4*)&g_hs[pos0 * 1024] + idx4);
        }
        __syncthreads();

        if (tid < 256) {
            ull acc2[PPC];
            #pragma unroll
            for (int p = 0; p < PPC; ++p) acc2[p] = 0ull;

            const ulonglong2* wrow = (const ulonglong2*)&W1[tid * 1024];
            for (int k4 = 0; k4 < 256; ++k4) {
                ulonglong2 w = __ldg(wrow + k4);
                #pragma unroll
                for (int p = 0; p < PPC; ++p) {
                    ulonglong2 hv = *(const ulonglong2*)&h_sm[p * 1024 + k4 * 4];
                    acc2[p] = fma2(w.x, hv.x, acc2[p]);
                    acc2[p] = fma2(w.y, hv.y, acc2[p]);
                }
            }
            float bv = b1[tid];
            #pragma unroll
            for (int p = 0; p < PPC; ++p) {
                float2 f = unpk(acc2[p]);
                logit_sm[p * 256 + tid] = f.x + f.y + bv;
            }
        }
        __syncthreads();

        if (wid < 8) {
            #pragma unroll
            for (int pp = 0; pp < 2; ++pp) {
                int p = wid * 2 + pp;
                const float* L = &logit_sm[p * 256];
                float vv[8];
                #pragma unroll
                for (int i = 0; i < 8; ++i) vv[i] = L[lane + 32 * i];
                float m = vv[0];
                #pragma unroll
                for (int i = 1; i < 8; ++i) m = fmaxf(m, vv[i]);
                for (int off = 16; off; off >>= 1)
                    m = fmaxf(m, __shfl_xor_sync(0xffffffffu, m, off));
                float s = 0.0f;
                #pragma unroll
                for (int i = 0; i < 8; ++i) s += expf(vv[i] - m);
                for (int off = 16; off; off >>= 1)
                    s += __shfl_xor_sync(0xffffffffu, s, off);
                if (lane == 0) {
                    int pos = pos0 + p;
                    int b   = pos & 7;
                    int t   = pos >> 3;
                    int y   = __ldg(&ys[b * T + t]);
                    redp[p] = (m + logf(s)) - L[y];
                }
            }
        }
        __syncthreads();
        if (tid == 0) {
            float ssum = 0.0f;
            #pragma unroll
            for (int p = 0; p < PPC; ++p) ssum += redp[p];
            cta_sum += ssum;
        }
        __syncthreads();
    }

    // ---- deterministic final reduction by the last-arriving CTA ----
    if (tid == 0) {
        g_partials[cta] = cta_sum;
        __threadfence();
        unsigned old = atomicAdd(&g_ticket, 1u);
        s_win = ((old % GRID) == (GRID - 1)) ? 1 : 0;
    }
    __syncthreads();
    if (s_win) {
        __threadfence();
        float* r2 = (float*)smem;
        if (tid < GRID) r2[tid] = __ldcg(&g_partials[tid]);
        __syncthreads();
        for (int off = 64; off; off >>= 1) {
            if (tid < off) r2[tid] += r2[tid + off];
            __syncthreads();
        }
        if (tid == 0) out[0] = r2[0] / (float)(B * T);
    }
}

// ---------------- launch ----------------
extern "C" void kernel_launch(void* const* d_in, const int* in_sizes, int n_in,
                              void* d_out, int out_size)
{
    const int*   Xs   = (const int*)d_in[0];
    const int*   ys   = (const int*)d_in[1];
    /* d_in[2] = predict (always 0 here) */
    const float* W_ih = (const float*)d_in[3];
    const float* W_hh = (const float*)d_in[4];
    const float* b_ih = (const float*)d_in[5];
    const float* b_hh = (const float*)d_in[6];
    const float* W1   = (const float*)d_in[7];
    const float* b1   = (const float*)d_in[8];
    float* out = (float*)d_out;

    cudaFuncSetAttribute(charrnn_kernel,
                         cudaFuncAttributeMaxDynamicSharedMemorySize, SMEM_DYN);

    charrnn_kernel<<<GRID, NTHR, SMEM_DYN>>>(Xs, ys, W_ih, W_hh, b_ih, b_hh,
                                             W1, b1, out);
    (void)in_sizes; (void)n_in; (void)out_size;
}